// round 2
// baseline (speedup 1.0000x reference)
#include <cuda_runtime.h>
#include <math.h>

#define QLEN  1024
#define BATCH 4
#define DMODEL 1024
#define NH    16
#define HD    64
#define MEMLEN 512
#define KLEN  1536
#define MLPD  4096
#define QKV3  3072
#define ATT_SCALE 0.125f
#define LNEPS 1e-5f

// ---------------- scratch (static device globals; no allocation) ----------------
__device__ float g_cat[(size_t)KLEN * BATCH * DMODEL];           //  25 MB
__device__ float g_qkv[(size_t)KLEN * BATCH * QKV3];             //  75 MB
__device__ float g_rp [(size_t)KLEN * DMODEL];                   //   6 MB
__device__ float g_AC [(size_t)BATCH * NH * QLEN * KLEN];        // 403 MB (reused as attn)
__device__ float g_BD [(size_t)BATCH * NH * QLEN * KLEN];        // 403 MB
__device__ float g_ctx[(size_t)QLEN * BATCH * DMODEL];           //  17 MB
__device__ float g_y  [(size_t)QLEN * BATCH * DMODEL];
__device__ float g_x  [(size_t)QLEN * BATCH * DMODEL];
__device__ float g_h  [(size_t)QLEN * BATCH * MLPD];             //  67 MB
__device__ float g_y2 [(size_t)QLEN * BATCH * DMODEL];

// ---------------- concat: cat = [mem; inputs] along klen ----------------
__global__ void concat_kernel(const float* __restrict__ mem,
                              const float* __restrict__ inp,
                              float* __restrict__ cat) {
    size_t n_mem = (size_t)MEMLEN * BATCH * DMODEL;
    size_t n_tot = (size_t)KLEN   * BATCH * DMODEL;
    for (size_t idx = (size_t)blockIdx.x * blockDim.x + threadIdx.x;
         idx < n_tot; idx += (size_t)gridDim.x * blockDim.x) {
        cat[idx] = (idx < n_mem) ? mem[idx] : inp[idx - n_mem];
    }
}

// ---------------- generic SGEMM: C = A[M,K] @ B[K,N] (+bias)(+relu) ----------------
// 64x64 tile, BK=16, 256 threads, 4x4 per thread
__global__ __launch_bounds__(256) void sgemm_kernel(
    const float* __restrict__ A, const float* __restrict__ B,
    float* __restrict__ C, const float* __restrict__ bias,
    int M, int N, int K, int relu)
{
    __shared__ float As[16][65];
    __shared__ float Bs[16][65];
    int tx = threadIdx.x, ty = threadIdx.y;
    int tid = ty * 16 + tx;
    int row0 = blockIdx.y * 64;
    int col0 = blockIdx.x * 64;
    float acc[4][4] = {};
    for (int k0 = 0; k0 < K; k0 += 16) {
        #pragma unroll
        for (int t = 0; t < 4; t++) {
            int idx = tid + t * 256;            // 0..1023
            int r = idx >> 4, c = idx & 15;     // A tile is 64 rows x 16 cols
            As[c][r] = A[(size_t)(row0 + r) * K + k0 + c];
        }
        #pragma unroll
        for (int t = 0; t < 4; t++) {
            int idx = tid + t * 256;
            int r = idx >> 6, c = idx & 63;     // B tile is 16 rows x 64 cols
            Bs[r][c] = B[(size_t)(k0 + r) * N + col0 + c];
        }
        __syncthreads();
        #pragma unroll
        for (int k = 0; k < 16; k++) {
            float a[4], b[4];
            #pragma unroll
            for (int i = 0; i < 4; i++) a[i] = As[k][ty * 4 + i];
            #pragma unroll
            for (int j = 0; j < 4; j++) b[j] = Bs[k][tx * 4 + j];
            #pragma unroll
            for (int i = 0; i < 4; i++)
                #pragma unroll
                for (int j = 0; j < 4; j++)
                    acc[i][j] += a[i] * b[j];
        }
        __syncthreads();
    }
    #pragma unroll
    for (int i = 0; i < 4; i++) {
        int r = row0 + ty * 4 + i;
        #pragma unroll
        for (int j = 0; j < 4; j++) {
            int c = col0 + tx * 4 + j;
            float v = acc[i][j];
            if (bias) v += bias[c];
            if (relu) v = fmaxf(v, 0.0f);
            C[(size_t)r * N + c] = v;
        }
    }
}

// ---------------- attention scores: AC = (q+u)K^T, BD = (q+v)R^T (unshifted) ----------------
// grid: (KLEN/64, QLEN/64, B*NH), block (16,16)
__global__ __launch_bounds__(256) void score_kernel(
    const float* __restrict__ qkv, const float* __restrict__ rp,
    const float* __restrict__ uvec, const float* __restrict__ vvec,
    float* __restrict__ AC, float* __restrict__ BD)
{
    __shared__ float Qs[64][65];
    __shared__ float Bs[64][65];
    __shared__ float su[64], sv[64];
    int bh = blockIdx.z;
    int b = bh / NH, h = bh % NH;
    int i0 = blockIdx.y * 64;
    int j0 = blockIdx.x * 64;
    int tx = threadIdx.x, ty = threadIdx.y;
    int tid = ty * 16 + tx;
    if (tid < 64) { su[tid] = uvec[h * HD + tid]; sv[tid] = vvec[h * HD + tid]; }
    // Q tile (raw q, head h), rows MEM+i0 .. MEM+i0+63
    #pragma unroll
    for (int t = 0; t < 16; t++) {
        int idx = tid + t * 256; int r = idx >> 6, c = idx & 63;
        Qs[r][c] = qkv[((size_t)(MEMLEN + i0 + r) * BATCH + b) * QKV3 + h * HD + c];
    }
    // K tile
    #pragma unroll
    for (int t = 0; t < 16; t++) {
        int idx = tid + t * 256; int r = idx >> 6, c = idx & 63;
        Bs[r][c] = qkv[((size_t)(j0 + r) * BATCH + b) * QKV3 + DMODEL + h * HD + c];
    }
    __syncthreads();
    float acc[4][4] = {};
    #pragma unroll
    for (int k = 0; k < 64; k++) {
        float uk = su[k];
        float a[4], bb[4];
        #pragma unroll
        for (int i = 0; i < 4; i++) a[i]  = Qs[ty * 4 + i][k] + uk;
        #pragma unroll
        for (int j = 0; j < 4; j++) bb[j] = Bs[tx * 4 + j][k];
        #pragma unroll
        for (int i = 0; i < 4; i++)
            #pragma unroll
            for (int j = 0; j < 4; j++)
                acc[i][j] += a[i] * bb[j];
    }
    {
        float* acp = AC + ((size_t)bh * QLEN + i0) * KLEN + j0;
        #pragma unroll
        for (int i = 0; i < 4; i++)
            #pragma unroll
            for (int j = 0; j < 4; j++)
                acp[(size_t)(ty * 4 + i) * KLEN + tx * 4 + j] = acc[i][j];
    }
    __syncthreads();
    // R tile (shared across batch)
    #pragma unroll
    for (int t = 0; t < 16; t++) {
        int idx = tid + t * 256; int r = idx >> 6, c = idx & 63;
        Bs[r][c] = rp[(size_t)(j0 + r) * DMODEL + h * HD + c];
    }
    __syncthreads();
    #pragma unroll
    for (int i = 0; i < 4; i++)
        #pragma unroll
        for (int j = 0; j < 4; j++) acc[i][j] = 0.0f;
    #pragma unroll
    for (int k = 0; k < 64; k++) {
        float vk = sv[k];
        float a[4], bb[4];
        #pragma unroll
        for (int i = 0; i < 4; i++) a[i]  = Qs[ty * 4 + i][k] + vk;
        #pragma unroll
        for (int j = 0; j < 4; j++) bb[j] = Bs[tx * 4 + j][k];
        #pragma unroll
        for (int i = 0; i < 4; i++)
            #pragma unroll
            for (int j = 0; j < 4; j++)
                acc[i][j] += a[i] * bb[j];
    }
    {
        float* bdp = BD + ((size_t)bh * QLEN + i0) * KLEN + j0;
        #pragma unroll
        for (int i = 0; i < 4; i++)
            #pragma unroll
            for (int j = 0; j < 4; j++)
                bdp[(size_t)(ty * 4 + i) * KLEN + tx * 4 + j] = acc[i][j];
    }
}

// ---------------- masked softmax with rel-shift gather; attn written in-place to AC ------
// grid (QLEN, B*NH), block 256
__global__ __launch_bounds__(256) void softmax_kernel(
    float* __restrict__ AC, const float* __restrict__ BD)
{
    int i  = blockIdx.x;
    int bh = blockIdx.y;
    float*       ac = AC + ((size_t)bh * QLEN + i) * KLEN;
    const float* bd = BD + ((size_t)bh * QLEN + i) * KLEN;
    int nvalid = i + MEMLEN + 1;          // j <= i + MEM
    int shift  = QLEN - 1 - i;            // rel-shift gather offset
    __shared__ float s[KLEN];
    __shared__ float red[256];
    int tid = threadIdx.x;
    float lm = -1e30f;
    for (int j = tid; j < KLEN; j += 256) {
        float vv = -1e30f;
        if (j < nvalid) vv = ATT_SCALE * (ac[j] + bd[j + shift]);
        s[j] = vv;
        lm = fmaxf(lm, vv);
    }
    red[tid] = lm; __syncthreads();
    for (int o = 128; o > 0; o >>= 1) {
        if (tid < o) red[tid] = fmaxf(red[tid], red[tid + o]);
        __syncthreads();
    }
    float mx = red[0]; __syncthreads();
    float ls = 0.0f;
    for (int j = tid; j < KLEN; j += 256) {
        float e = (j < nvalid) ? __expf(s[j] - mx) : 0.0f;
        s[j] = e; ls += e;
    }
    red[tid] = ls; __syncthreads();
    for (int o = 128; o > 0; o >>= 1) {
        if (tid < o) red[tid] += red[tid + o];
        __syncthreads();
    }
    float inv = 1.0f / red[0]; __syncthreads();
    for (int j = tid; j < KLEN; j += 256) ac[j] = s[j] * inv;
}

// ---------------- ctx = attn @ V  (per b,h) ----------------
// grid (QLEN/64, B*NH), block (16,16)
__global__ __launch_bounds__(256) void ctx_kernel(
    const float* __restrict__ attn, const float* __restrict__ qkv,
    float* __restrict__ ctx)
{
    __shared__ float As[16][65];  // As[k][i]
    __shared__ float Bs[16][65];  // Bs[k][d]
    int bh = blockIdx.y;
    int b = bh / NH, h = bh % NH;
    int i0 = blockIdx.x * 64;
    int tx = threadIdx.x, ty = threadIdx.y;
    int tid = ty * 16 + tx;
    const float* ap = attn + ((size_t)bh * QLEN + i0) * KLEN;
    float acc[4][4] = {};
    for (int k0 = 0; k0 < KLEN; k0 += 16) {
        #pragma unroll
        for (int t = 0; t < 4; t++) {
            int idx = tid + t * 256; int r = idx >> 4, c = idx & 15;
            As[c][r] = ap[(size_t)r * KLEN + k0 + c];
        }
        #pragma unroll
        for (int t = 0; t < 4; t++) {
            int idx = tid + t * 256; int r = idx >> 6, c = idx & 63;
            Bs[r][c] = qkv[((size_t)(k0 + r) * BATCH + b) * QKV3 + 2 * DMODEL + h * HD + c];
        }
        __syncthreads();
        #pragma unroll
        for (int k = 0; k < 16; k++) {
            float a[4], bb[4];
            #pragma unroll
            for (int i = 0; i < 4; i++) a[i]  = As[k][ty * 4 + i];
            #pragma unroll
            for (int j = 0; j < 4; j++) bb[j] = Bs[k][tx * 4 + j];
            #pragma unroll
            for (int i = 0; i < 4; i++)
                #pragma unroll
                for (int j = 0; j < 4; j++)
                    acc[i][j] += a[i] * bb[j];
        }
        __syncthreads();
    }
    #pragma unroll
    for (int i = 0; i < 4; i++)
        #pragma unroll
        for (int j = 0; j < 4; j++)
            ctx[((size_t)(i0 + ty * 4 + i) * BATCH + b) * DMODEL + h * HD + tx * 4 + j] = acc[i][j];
}

// ---------------- layernorm: out = LN(a + b) * g + beta ----------------
// grid rows (4096), block 256, DMODEL=1024 -> 4 per thread
__global__ __launch_bounds__(256) void ln_kernel(
    const float* __restrict__ a, const float* __restrict__ bres,
    const float* __restrict__ g, const float* __restrict__ beta,
    float* __restrict__ out)
{
    int row = blockIdx.x;
    int tid = threadIdx.x;
    const float* ap = a    + (size_t)row * DMODEL;
    const float* bp = bres + (size_t)row * DMODEL;
    float x[4];
    float sum = 0.0f;
    #pragma unroll
    for (int t = 0; t < 4; t++) {
        int c = tid + t * 256;
        x[t] = ap[c] + bp[c];
        sum += x[t];
    }
    __shared__ float red[256];
    red[tid] = sum; __syncthreads();
    for (int o = 128; o > 0; o >>= 1) {
        if (tid < o) red[tid] += red[tid + o];
        __syncthreads();
    }
    float mean = red[0] * (1.0f / DMODEL); __syncthreads();
    float vs = 0.0f;
    #pragma unroll
    for (int t = 0; t < 4; t++) { float d = x[t] - mean; vs += d * d; }
    red[tid] = vs; __syncthreads();
    for (int o = 128; o > 0; o >>= 1) {
        if (tid < o) red[tid] += red[tid + o];
        __syncthreads();
    }
    float inv = rsqrtf(red[0] * (1.0f / DMODEL) + LNEPS);
    #pragma unroll
    for (int t = 0; t < 4; t++) {
        int c = tid + t * 256;
        out[(size_t)row * DMODEL + c] = (x[t] - mean) * inv * g[c] + beta[c];
    }
}

// ---------------- launch ----------------
extern "C" void kernel_launch(void* const* d_in, const int* in_sizes, int n_in,
                              void* d_out, int out_size)
{
    const float* inputs = (const float*)d_in[0];
    const float* r      = (const float*)d_in[1];
    const float* u      = (const float*)d_in[2];
    const float* v      = (const float*)d_in[3];
    const float* mem    = (const float*)d_in[4];
    // d_in[5] = attn_mask (deterministic, recomputed in-kernel)
    const float* W_qkv  = (const float*)d_in[6];
    const float* W_r    = (const float*)d_in[7];
    const float* W_o    = (const float*)d_in[8];
    const float* ln1_g  = (const float*)d_in[9];
    const float* ln1_b  = (const float*)d_in[10];
    const float* ln2_g  = (const float*)d_in[11];
    const float* ln2_b  = (const float*)d_in[12];
    const float* W1     = (const float*)d_in[13];
    const float* b1     = (const float*)d_in[14];
    const float* W2     = (const float*)d_in[15];
    const float* b2     = (const float*)d_in[16];
    float* out = (float*)d_out;

    float *cat, *qkv, *rp, *AC, *BD, *ctx, *y, *x, *hbuf, *y2;
    cudaGetSymbolAddress((void**)&cat,  g_cat);
    cudaGetSymbolAddress((void**)&qkv,  g_qkv);
    cudaGetSymbolAddress((void**)&rp,   g_rp);
    cudaGetSymbolAddress((void**)&AC,   g_AC);
    cudaGetSymbolAddress((void**)&BD,   g_BD);
    cudaGetSymbolAddress((void**)&ctx,  g_ctx);
    cudaGetSymbolAddress((void**)&y,    g_y);
    cudaGetSymbolAddress((void**)&x,    g_x);
    cudaGetSymbolAddress((void**)&hbuf, g_h);
    cudaGetSymbolAddress((void**)&y2,   g_y2);

    dim3 blk2(16, 16);

    // 1. cat = [mem; inputs]
    concat_kernel<<<4096, 256>>>(mem, inputs, cat);

    // 2. qkv = cat @ W_qkv          [6144 x 3072 x 1024]
    sgemm_kernel<<<dim3(QKV3 / 64, (KLEN * BATCH) / 64), blk2>>>(
        cat, W_qkv, qkv, nullptr, KLEN * BATCH, QKV3, DMODEL, 0);

    // 3. rp = r @ W_r               [1536 x 1024 x 1024]
    sgemm_kernel<<<dim3(DMODEL / 64, KLEN / 64), blk2>>>(
        r, W_r, rp, nullptr, KLEN, DMODEL, DMODEL, 0);

    // 4. AC / BD scores             batched over 64 (b,h)
    score_kernel<<<dim3(KLEN / 64, QLEN / 64, BATCH * NH), blk2>>>(
        qkv, rp, u, v, AC, BD);

    // 5. masked softmax + rel-shift (attn -> AC in-place)
    softmax_kernel<<<dim3(QLEN, BATCH * NH), 256>>>(AC, BD);

    // 6. ctx = attn @ V
    ctx_kernel<<<dim3(QLEN / 64, BATCH * NH), blk2>>>(AC, qkv, ctx);

    // 7. y = ctx @ W_o              [4096 x 1024 x 1024]
    sgemm_kernel<<<dim3(DMODEL / 64, (QLEN * BATCH) / 64), blk2>>>(
        ctx, W_o, y, nullptr, QLEN * BATCH, DMODEL, DMODEL, 0);

    // 8. x = LN1(inputs + y)
    ln_kernel<<<QLEN * BATCH, 256>>>(inputs, y, ln1_g, ln1_b, x);

    // 9. h = relu(x @ W1 + b1)      [4096 x 4096 x 1024]
    sgemm_kernel<<<dim3(MLPD / 64, (QLEN * BATCH) / 64), blk2>>>(
        x, W1, hbuf, b1, QLEN * BATCH, MLPD, DMODEL, 1);

    // 10. y2 = h @ W2 + b2          [4096 x 1024 x 4096]
    sgemm_kernel<<<dim3(DMODEL / 64, (QLEN * BATCH) / 64), blk2>>>(
        hbuf, W2, y2, b2, QLEN * BATCH, DMODEL, MLPD, 0);

    // 11. out = LN2(x + y2)
    ln_kernel<<<QLEN * BATCH, 256>>>(x, y2, ln2_g, ln2_b, out);
}

// round 3
// speedup vs baseline: 3.1621x; 3.1621x over previous
#include <cuda_runtime.h>
#include <math.h>

#define QLEN  1024
#define BATCH 4
#define DMODEL 1024
#define NH    16
#define HD    64
#define MEMLEN 512
#define KLEN  1536
#define MLPD  4096
#define QKV3  3072
#define ATT_SCALE 0.125f
#define LNEPS 1e-5f

// ---------------- scratch (static device globals; no allocation) ----------------
__device__ float g_cat[(size_t)KLEN * BATCH * DMODEL];
__device__ float g_qkv[(size_t)KLEN * BATCH * QKV3];
__device__ float g_rp [(size_t)KLEN * DMODEL];
__device__ float g_AC [(size_t)BATCH * NH * QLEN * KLEN];   // reused as attn
__device__ float g_BD [(size_t)BATCH * NH * QLEN * KLEN];
__device__ float g_ctx[(size_t)QLEN * BATCH * DMODEL];
__device__ float g_y  [(size_t)QLEN * BATCH * DMODEL];
__device__ float g_x  [(size_t)QLEN * BATCH * DMODEL];
__device__ float g_h  [(size_t)QLEN * BATCH * MLPD];
__device__ float g_y2 [(size_t)QLEN * BATCH * DMODEL];

// ---------------- helpers ----------------
__device__ __forceinline__ unsigned f2tf(float x) {
    unsigned r; asm("cvt.rna.tf32.f32 %0, %1;" : "=r"(r) : "f"(x)); return r;
}
__device__ __forceinline__ void mma8(float c[4],
    unsigned a0, unsigned a1, unsigned a2, unsigned a3, unsigned b0, unsigned b1) {
    asm volatile(
        "mma.sync.aligned.m16n8k8.row.col.f32.tf32.tf32.f32 "
        "{%0,%1,%2,%3},{%4,%5,%6,%7},{%8,%9},{%0,%1,%2,%3};"
        : "+f"(c[0]), "+f"(c[1]), "+f"(c[2]), "+f"(c[3])
        : "r"(a0), "r"(a1), "r"(a2), "r"(a3), "r"(b0), "r"(b1));
}

// ---------------- concat: cat = [mem; inputs] ----------------
__global__ void concat_kernel(const float* __restrict__ mem,
                              const float* __restrict__ inp,
                              float* __restrict__ cat) {
    size_t n_mem = (size_t)MEMLEN * BATCH * DMODEL;
    size_t n_tot = (size_t)KLEN   * BATCH * DMODEL;
    for (size_t idx = (size_t)blockIdx.x * blockDim.x + threadIdx.x;
         idx < n_tot; idx += (size_t)gridDim.x * blockDim.x) {
        cat[idx] = (idx < n_mem) ? mem[idx] : inp[idx - n_mem];
    }
}

// ---------------- tf32 GEMM: C = A[M,K] @ B[K,N] (+bias)(+relu) ----------------
// 128x128 tile, BK=32, 256 threads (8 warps as 2m x 4n, warp tile 64x32)
#define ASTR 36
#define BSTR 136
__global__ __launch_bounds__(256, 2) void gemm_tf32(
    const float* __restrict__ A, const float* __restrict__ B,
    float* __restrict__ C, const float* __restrict__ bias,
    int M, int N, int K, int relu)
{
    __shared__ unsigned As[128 * ASTR];   // [m][k]
    __shared__ unsigned Bs[32 * BSTR];    // [k][n]
    int tid = threadIdx.x, lane = tid & 31, warp = tid >> 5;
    int qid = lane >> 2, qt = lane & 3;
    int wm = (warp >> 2) * 64, wn = (warp & 3) * 32;
    int m0 = blockIdx.y * 128, n0 = blockIdx.x * 128;
    float c[4][4][4];
    #pragma unroll
    for (int mi = 0; mi < 4; mi++)
        #pragma unroll
        for (int ni = 0; ni < 4; ni++)
            #pragma unroll
            for (int t = 0; t < 4; t++) c[mi][ni][t] = 0.0f;

    for (int k0 = 0; k0 < K; k0 += 32) {
        #pragma unroll
        for (int i = 0; i < 4; i++) {
            int id = tid + i * 256; int r = id >> 3, c4 = id & 7;
            float4 v = *(const float4*)(A + (size_t)(m0 + r) * K + k0 + c4 * 4);
            uint4 t = { f2tf(v.x), f2tf(v.y), f2tf(v.z), f2tf(v.w) };
            *(uint4*)&As[r * ASTR + c4 * 4] = t;
        }
        #pragma unroll
        for (int i = 0; i < 4; i++) {
            int id = tid + i * 256; int r = id >> 5, c4 = id & 31;
            float4 v = *(const float4*)(B + (size_t)(k0 + r) * N + n0 + c4 * 4);
            uint4 t = { f2tf(v.x), f2tf(v.y), f2tf(v.z), f2tf(v.w) };
            *(uint4*)&Bs[r * BSTR + c4 * 4] = t;
        }
        __syncthreads();
        #pragma unroll
        for (int kk = 0; kk < 4; kk++) {
            unsigned a[4][4], bf[4][2];
            #pragma unroll
            for (int mi = 0; mi < 4; mi++) {
                int base = (wm + mi * 16 + qid) * ASTR + kk * 8 + qt;
                a[mi][0] = As[base];            a[mi][1] = As[base + 8 * ASTR];
                a[mi][2] = As[base + 4];        a[mi][3] = As[base + 8 * ASTR + 4];
            }
            #pragma unroll
            for (int ni = 0; ni < 4; ni++) {
                int base = (kk * 8 + qt) * BSTR + wn + ni * 8 + qid;
                bf[ni][0] = Bs[base]; bf[ni][1] = Bs[base + 4 * BSTR];
            }
            #pragma unroll
            for (int mi = 0; mi < 4; mi++)
                #pragma unroll
                for (int ni = 0; ni < 4; ni++)
                    mma8(c[mi][ni], a[mi][0], a[mi][1], a[mi][2], a[mi][3],
                         bf[ni][0], bf[ni][1]);
        }
        __syncthreads();
    }
    #pragma unroll
    for (int mi = 0; mi < 4; mi++) {
        int row = m0 + wm + mi * 16 + qid;
        #pragma unroll
        for (int ni = 0; ni < 4; ni++) {
            int col = n0 + wn + ni * 8 + qt * 2;
            float b0 = bias ? bias[col] : 0.0f;
            float b1 = bias ? bias[col + 1] : 0.0f;
            float v00 = c[mi][ni][0] + b0, v01 = c[mi][ni][1] + b1;
            float v10 = c[mi][ni][2] + b0, v11 = c[mi][ni][3] + b1;
            if (relu) { v00 = fmaxf(v00, 0.f); v01 = fmaxf(v01, 0.f);
                        v10 = fmaxf(v10, 0.f); v11 = fmaxf(v11, 0.f); }
            C[(size_t)row * N + col]           = v00;
            C[(size_t)row * N + col + 1]       = v01;
            C[(size_t)(row + 8) * N + col]     = v10;
            C[(size_t)(row + 8) * N + col + 1] = v11;
        }
    }
}

// ---------------- tf32 score kernel: AC = (q+u)K^T, BD = (q+v)R^T ----------------
// block tile 128(q) x 128(k), full K=64, grid (KLEN/128, QLEN/128, B*NH)
#define SSTR 68
__global__ __launch_bounds__(256) void score_tf32(
    const float* __restrict__ qkv, const float* __restrict__ rp,
    const float* __restrict__ uvec, const float* __restrict__ vvec,
    float* __restrict__ AC, float* __restrict__ BD)
{
    extern __shared__ unsigned dyn[];
    float*    Qs = (float*)dyn;          // [m][d] raw fp32, 128 x 68
    unsigned* Ks = dyn + 128 * SSTR;     // [j][d] tf32,     128 x 68
    __shared__ float su[64], sv[64];
    int tid = threadIdx.x, lane = tid & 31, warp = tid >> 5;
    int qid = lane >> 2, qt = lane & 3;
    int wm = (warp >> 2) * 64, wn = (warp & 3) * 32;
    int bh = blockIdx.z, b = bh >> 4, h = bh & 15;
    int i0 = blockIdx.y * 128, j0 = blockIdx.x * 128;
    if (tid < 64) { su[tid] = uvec[h * 64 + tid]; sv[tid] = vvec[h * 64 + tid]; }

    #pragma unroll
    for (int i = 0; i < 8; i++) {      // Q tile (raw)
        int id = tid + i * 256; int r = id >> 4, c4 = id & 15;
        float4 v = *(const float4*)(qkv + ((size_t)(MEMLEN + i0 + r) * BATCH + b) * QKV3 + h * 64 + c4 * 4);
        *(float4*)&Qs[r * SSTR + c4 * 4] = v;
    }
    #pragma unroll
    for (int i = 0; i < 8; i++) {      // K tile (tf32)
        int id = tid + i * 256; int r = id >> 4, c4 = id & 15;
        float4 v = *(const float4*)(qkv + ((size_t)(j0 + r) * BATCH + b) * QKV3 + DMODEL + h * 64 + c4 * 4);
        uint4 t = { f2tf(v.x), f2tf(v.y), f2tf(v.z), f2tf(v.w) };
        *(uint4*)&Ks[r * SSTR + c4 * 4] = t;
    }
    __syncthreads();

    float c[4][4][4];
    #pragma unroll
    for (int mi = 0; mi < 4; mi++)
        #pragma unroll
        for (int ni = 0; ni < 4; ni++)
            #pragma unroll
            for (int t = 0; t < 4; t++) c[mi][ni][t] = 0.0f;

    #pragma unroll
    for (int kk = 0; kk < 8; kk++) {
        float u0 = su[kk * 8 + qt], u1 = su[kk * 8 + qt + 4];
        unsigned a[4][4], bf[4][2];
        #pragma unroll
        for (int mi = 0; mi < 4; mi++) {
            int base = (wm + mi * 16 + qid) * SSTR + kk * 8 + qt;
            a[mi][0] = f2tf(Qs[base] + u0);
            a[mi][1] = f2tf(Qs[base + 8 * SSTR] + u0);
            a[mi][2] = f2tf(Qs[base + 4] + u1);
            a[mi][3] = f2tf(Qs[base + 8 * SSTR + 4] + u1);
        }
        #pragma unroll
        for (int ni = 0; ni < 4; ni++) {
            int base = (wn + ni * 8 + qid) * SSTR + kk * 8 + qt;
            bf[ni][0] = Ks[base]; bf[ni][1] = Ks[base + 4];
        }
        #pragma unroll
        for (int mi = 0; mi < 4; mi++)
            #pragma unroll
            for (int ni = 0; ni < 4; ni++)
                mma8(c[mi][ni], a[mi][0], a[mi][1], a[mi][2], a[mi][3],
                     bf[ni][0], bf[ni][1]);
    }
    #pragma unroll
    for (int mi = 0; mi < 4; mi++) {
        int row = i0 + wm + mi * 16 + qid;
        #pragma unroll
        for (int ni = 0; ni < 4; ni++) {
            int col = j0 + wn + ni * 8 + qt * 2;
            float* p = AC + ((size_t)bh * QLEN + row) * KLEN + col;
            p[0] = c[mi][ni][0]; p[1] = c[mi][ni][1];
            p[(size_t)8 * KLEN] = c[mi][ni][2]; p[(size_t)8 * KLEN + 1] = c[mi][ni][3];
        }
    }
    __syncthreads();
    #pragma unroll
    for (int i = 0; i < 8; i++) {      // R tile (tf32) overwrites Ks
        int id = tid + i * 256; int r = id >> 4, c4 = id & 15;
        float4 v = *(const float4*)(rp + (size_t)(j0 + r) * DMODEL + h * 64 + c4 * 4);
        uint4 t = { f2tf(v.x), f2tf(v.y), f2tf(v.z), f2tf(v.w) };
        *(uint4*)&Ks[r * SSTR + c4 * 4] = t;
    }
    __syncthreads();
    #pragma unroll
    for (int mi = 0; mi < 4; mi++)
        #pragma unroll
        for (int ni = 0; ni < 4; ni++)
            #pragma unroll
            for (int t = 0; t < 4; t++) c[mi][ni][t] = 0.0f;
    #pragma unroll
    for (int kk = 0; kk < 8; kk++) {
        float v0 = sv[kk * 8 + qt], v1 = sv[kk * 8 + qt + 4];
        unsigned a[4][4], bf[4][2];
        #pragma unroll
        for (int mi = 0; mi < 4; mi++) {
            int base = (wm + mi * 16 + qid) * SSTR + kk * 8 + qt;
            a[mi][0] = f2tf(Qs[base] + v0);
            a[mi][1] = f2tf(Qs[base + 8 * SSTR] + v0);
            a[mi][2] = f2tf(Qs[base + 4] + v1);
            a[mi][3] = f2tf(Qs[base + 8 * SSTR + 4] + v1);
        }
        #pragma unroll
        for (int ni = 0; ni < 4; ni++) {
            int base = (wn + ni * 8 + qid) * SSTR + kk * 8 + qt;
            bf[ni][0] = Ks[base]; bf[ni][1] = Ks[base + 4];
        }
        #pragma unroll
        for (int mi = 0; mi < 4; mi++)
            #pragma unroll
            for (int ni = 0; ni < 4; ni++)
                mma8(c[mi][ni], a[mi][0], a[mi][1], a[mi][2], a[mi][3],
                     bf[ni][0], bf[ni][1]);
    }
    #pragma unroll
    for (int mi = 0; mi < 4; mi++) {
        int row = i0 + wm + mi * 16 + qid;
        #pragma unroll
        for (int ni = 0; ni < 4; ni++) {
            int col = j0 + wn + ni * 8 + qt * 2;
            float* p = BD + ((size_t)bh * QLEN + row) * KLEN + col;
            p[0] = c[mi][ni][0]; p[1] = c[mi][ni][1];
            p[(size_t)8 * KLEN] = c[mi][ni][2]; p[(size_t)8 * KLEN + 1] = c[mi][ni][3];
        }
    }
}

// ---------------- masked softmax with rel-shift gather; attn -> AC in-place ------
__global__ __launch_bounds__(256) void softmax_kernel(
    float* __restrict__ AC, const float* __restrict__ BD)
{
    int i  = blockIdx.x;
    int bh = blockIdx.y;
    float*       ac = AC + ((size_t)bh * QLEN + i) * KLEN;
    const float* bd = BD + ((size_t)bh * QLEN + i) * KLEN;
    int nvalid = i + MEMLEN + 1;
    int shift  = QLEN - 1 - i;
    __shared__ float s[KLEN];
    __shared__ float red[256];
    int tid = threadIdx.x;
    float lm = -1e30f;
    for (int j = tid; j < KLEN; j += 256) {
        float vv = -1e30f;
        if (j < nvalid) vv = ATT_SCALE * (ac[j] + bd[j + shift]);
        s[j] = vv;
        lm = fmaxf(lm, vv);
    }
    red[tid] = lm; __syncthreads();
    for (int o = 128; o > 0; o >>= 1) {
        if (tid < o) red[tid] = fmaxf(red[tid], red[tid + o]);
        __syncthreads();
    }
    float mx = red[0]; __syncthreads();
    float ls = 0.0f;
    for (int j = tid; j < KLEN; j += 256) {
        float e = (j < nvalid) ? __expf(s[j] - mx) : 0.0f;
        s[j] = e; ls += e;
    }
    red[tid] = ls; __syncthreads();
    for (int o = 128; o > 0; o >>= 1) {
        if (tid < o) red[tid] += red[tid + o];
        __syncthreads();
    }
    float inv = 1.0f / red[0]; __syncthreads();
    for (int j = tid; j < KLEN; j += 256) ac[j] = s[j] * inv;
}

// ---------------- tf32 ctx kernel: ctx = attn @ V  (per b,h) ----------------
// block tile 128(m) x 64(n), BK=32; 8 warps as 4m x 2n (warp 32x32)
#define CAS 36
#define CBS 72
__global__ __launch_bounds__(256) void ctx_tf32(
    const float* __restrict__ attn, const float* __restrict__ qkv,
    float* __restrict__ ctx)
{
    __shared__ unsigned As[128 * CAS];
    __shared__ unsigned Bs[32 * CBS];
    int tid = threadIdx.x, lane = tid & 31, warp = tid >> 5;
    int qid = lane >> 2, qt = lane & 3;
    int wm = (warp >> 1) * 32, wn = (warp & 1) * 32;
    int bh = blockIdx.y, b = bh >> 4, h = bh & 15;
    int i0 = blockIdx.x * 128;
    const float* ap = attn + ((size_t)bh * QLEN + i0) * KLEN;
    float c[2][4][4];
    #pragma unroll
    for (int mi = 0; mi < 2; mi++)
        #pragma unroll
        for (int ni = 0; ni < 4; ni++)
            #pragma unroll
            for (int t = 0; t < 4; t++) c[mi][ni][t] = 0.0f;

    for (int k0 = 0; k0 < KLEN; k0 += 32) {
        #pragma unroll
        for (int i = 0; i < 4; i++) {
            int id = tid + i * 256; int r = id >> 3, c4 = id & 7;
            float4 v = *(const float4*)(ap + (size_t)r * KLEN + k0 + c4 * 4);
            uint4 t = { f2tf(v.x), f2tf(v.y), f2tf(v.z), f2tf(v.w) };
            *(uint4*)&As[r * CAS + c4 * 4] = t;
        }
        #pragma unroll
        for (int i = 0; i < 2; i++) {
            int id = tid + i * 256; int r = id >> 4, c4 = id & 15;
            float4 v = *(const float4*)(qkv + ((size_t)(k0 + r) * BATCH + b) * QKV3 + 2 * DMODEL + h * 64 + c4 * 4);
            uint4 t = { f2tf(v.x), f2tf(v.y), f2tf(v.z), f2tf(v.w) };
            *(uint4*)&Bs[r * CBS + c4 * 4] = t;
        }
        __syncthreads();
        #pragma unroll
        for (int kk = 0; kk < 4; kk++) {
            unsigned a[2][4], bf[4][2];
            #pragma unroll
            for (int mi = 0; mi < 2; mi++) {
                int base = (wm + mi * 16 + qid) * CAS + kk * 8 + qt;
                a[mi][0] = As[base];     a[mi][1] = As[base + 8 * CAS];
                a[mi][2] = As[base + 4]; a[mi][3] = As[base + 8 * CAS + 4];
            }
            #pragma unroll
            for (int ni = 0; ni < 4; ni++) {
                int base = (kk * 8 + qt) * CBS + wn + ni * 8 + qid;
                bf[ni][0] = Bs[base]; bf[ni][1] = Bs[base + 4 * CBS];
            }
            #pragma unroll
            for (int mi = 0; mi < 2; mi++)
                #pragma unroll
                for (int ni = 0; ni < 4; ni++)
                    mma8(c[mi][ni], a[mi][0], a[mi][1], a[mi][2], a[mi][3],
                         bf[ni][0], bf[ni][1]);
        }
        __syncthreads();
    }
    #pragma unroll
    for (int mi = 0; mi < 2; mi++) {
        int row = i0 + wm + mi * 16 + qid;
        #pragma unroll
        for (int ni = 0; ni < 4; ni++) {
            int col = wn + ni * 8 + qt * 2;
            float* p = ctx + ((size_t)row * BATCH + b) * DMODEL + h * 64 + col;
            p[0] = c[mi][ni][0]; p[1] = c[mi][ni][1];
            float* p2 = ctx + ((size_t)(row + 8) * BATCH + b) * DMODEL + h * 64 + col;
            p2[0] = c[mi][ni][2]; p2[1] = c[mi][ni][3];
        }
    }
}

// ---------------- layernorm: out = LN(a + b) * g + beta ----------------
__global__ __launch_bounds__(256) void ln_kernel(
    const float* __restrict__ a, const float* __restrict__ bres,
    const float* __restrict__ g, const float* __restrict__ beta,
    float* __restrict__ out)
{
    int row = blockIdx.x;
    int tid = threadIdx.x;
    const float* ap = a    + (size_t)row * DMODEL;
    const float* bp = bres + (size_t)row * DMODEL;
    float x[4];
    float sum = 0.0f;
    #pragma unroll
    for (int t = 0; t < 4; t++) {
        int c = tid + t * 256;
        x[t] = ap[c] + bp[c];
        sum += x[t];
    }
    __shared__ float red[256];
    red[tid] = sum; __syncthreads();
    for (int o = 128; o > 0; o >>= 1) {
        if (tid < o) red[tid] += red[tid + o];
        __syncthreads();
    }
    float mean = red[0] * (1.0f / DMODEL); __syncthreads();
    float vs = 0.0f;
    #pragma unroll
    for (int t = 0; t < 4; t++) { float d = x[t] - mean; vs += d * d; }
    red[tid] = vs; __syncthreads();
    for (int o = 128; o > 0; o >>= 1) {
        if (tid < o) red[tid] += red[tid + o];
        __syncthreads();
    }
    float inv = rsqrtf(red[0] * (1.0f / DMODEL) + LNEPS);
    #pragma unroll
    for (int t = 0; t < 4; t++) {
        int c = tid + t * 256;
        out[(size_t)row * DMODEL + c] = (x[t] - mean) * inv * g[c] + beta[c];
    }
}

// ---------------- launch ----------------
extern "C" void kernel_launch(void* const* d_in, const int* in_sizes, int n_in,
                              void* d_out, int out_size)
{
    const float* inputs = (const float*)d_in[0];
    const float* r      = (const float*)d_in[1];
    const float* u      = (const float*)d_in[2];
    const float* v      = (const float*)d_in[3];
    const float* mem    = (const float*)d_in[4];
    const float* W_qkv  = (const float*)d_in[6];
    const float* W_r    = (const float*)d_in[7];
    const float* W_o    = (const float*)d_in[8];
    const float* ln1_g  = (const float*)d_in[9];
    const float* ln1_b  = (const float*)d_in[10];
    const float* ln2_g  = (const float*)d_in[11];
    const float* ln2_b  = (const float*)d_in[12];
    const float* W1     = (const float*)d_in[13];
    const float* b1     = (const float*)d_in[14];
    const float* W2     = (const float*)d_in[15];
    const float* b2     = (const float*)d_in[16];
    float* out = (float*)d_out;

    float *cat, *qkv, *rp, *AC, *BD, *ctx, *y, *x, *hbuf, *y2;
    cudaGetSymbolAddress((void**)&cat,  g_cat);
    cudaGetSymbolAddress((void**)&qkv,  g_qkv);
    cudaGetSymbolAddress((void**)&rp,   g_rp);
    cudaGetSymbolAddress((void**)&AC,   g_AC);
    cudaGetSymbolAddress((void**)&BD,   g_BD);
    cudaGetSymbolAddress((void**)&ctx,  g_ctx);
    cudaGetSymbolAddress((void**)&y,    g_y);
    cudaGetSymbolAddress((void**)&x,    g_x);
    cudaGetSymbolAddress((void**)&hbuf, g_h);
    cudaGetSymbolAddress((void**)&y2,   g_y2);

    const int score_smem = 2 * 128 * SSTR * 4;
    cudaFuncSetAttribute(score_tf32, cudaFuncAttributeMaxDynamicSharedMemorySize, score_smem);

    // 1. cat = [mem; inputs]
    concat_kernel<<<4096, 256>>>(mem, inputs, cat);

    // 2. qkv = cat @ W_qkv          [6144 x 3072 x 1024]
    gemm_tf32<<<dim3(QKV3 / 128, (KLEN * BATCH) / 128), 256>>>(
        cat, W_qkv, qkv, nullptr, KLEN * BATCH, QKV3, DMODEL, 0);

    // 3. rp = r @ W_r               [1536 x 1024 x 1024]
    gemm_tf32<<<dim3(DMODEL / 128, KLEN / 128), 256>>>(
        r, W_r, rp, nullptr, KLEN, DMODEL, DMODEL, 0);

    // 4. AC / BD scores             batched over 64 (b,h)
    score_tf32<<<dim3(KLEN / 128, QLEN / 128, BATCH * NH), 256, score_smem>>>(
        qkv, rp, u, v, AC, BD);

    // 5. masked softmax + rel-shift (attn -> AC in-place)
    softmax_kernel<<<dim3(QLEN, BATCH * NH), 256>>>(AC, BD);

    // 6. ctx = attn @ V
    ctx_tf32<<<dim3(QLEN / 128, BATCH * NH), 256>>>(AC, qkv, ctx);

    // 7. y = ctx @ W_o              [4096 x 1024 x 1024]
    gemm_tf32<<<dim3(DMODEL / 128, (QLEN * BATCH) / 128), 256>>>(
        ctx, W_o, y, nullptr, QLEN * BATCH, DMODEL, DMODEL, 0);

    // 8. x = LN1(inputs + y)
    ln_kernel<<<QLEN * BATCH, 256>>>(inputs, y, ln1_g, ln1_b, x);

    // 9. h = relu(x @ W1 + b1)      [4096 x 4096 x 1024]
    gemm_tf32<<<dim3(MLPD / 128, (QLEN * BATCH) / 128), 256>>>(
        x, W1, hbuf, b1, QLEN * BATCH, MLPD, DMODEL, 1);

    // 10. y2 = h @ W2 + b2          [4096 x 1024 x 4096]
    gemm_tf32<<<dim3(DMODEL / 128, (QLEN * BATCH) / 128), 256>>>(
        hbuf, W2, y2, b2, QLEN * BATCH, DMODEL, MLPD, 0);

    // 11. out = LN2(x + y2)
    ln_kernel<<<QLEN * BATCH, 256>>>(x, y2, ln2_g, ln2_b, out);
}

// round 5
// speedup vs baseline: 4.5201x; 1.4295x over previous
#include <cuda_runtime.h>
#include <math.h>

#define QLEN  1024
#define BATCH 4
#define DMODEL 1024
#define NH    16
#define HD    64
#define MEMLEN 512
#define KLEN  1536
#define MLPD  4096
#define QKV3  3072
#define ATT_SCALE 0.125f
#define LNEPS 1e-5f

// ---------------- scratch (static device globals; no allocation) ----------------
__device__ unsigned g_cat_t [(size_t)KLEN * BATCH * DMODEL];
__device__ unsigned g_qkv_t [(size_t)KLEN * BATCH * QKV3];
__device__ unsigned g_rp_t  [(size_t)KLEN * DMODEL];
__device__ unsigned g_qu    [(size_t)QLEN * BATCH * DMODEL];
__device__ unsigned g_qv    [(size_t)QLEN * BATCH * DMODEL];
__device__ float    g_BD    [(size_t)BATCH * NH * QLEN * KLEN];   // pre-shifted, pre-scaled
__device__ unsigned g_ctx_t [(size_t)QLEN * BATCH * DMODEL];
__device__ float    g_y     [(size_t)QLEN * BATCH * DMODEL];
__device__ float    g_x     [(size_t)QLEN * BATCH * DMODEL];
__device__ unsigned g_x_t   [(size_t)QLEN * BATCH * DMODEL];
__device__ unsigned g_h_t   [(size_t)QLEN * BATCH * MLPD];
__device__ float    g_y2    [(size_t)QLEN * BATCH * DMODEL];
__device__ unsigned g_wqkv_t[(size_t)DMODEL * QKV3];
__device__ unsigned g_wr_t  [(size_t)DMODEL * DMODEL];
__device__ unsigned g_wo_t  [(size_t)DMODEL * DMODEL];
__device__ unsigned g_w1_t  [(size_t)DMODEL * MLPD];
__device__ unsigned g_w2_t  [(size_t)MLPD * DMODEL];
__device__ unsigned g_r_t   [(size_t)KLEN * DMODEL];

// ---------------- helpers ----------------
__device__ __forceinline__ unsigned f2tf(float x) {
    unsigned r; asm("cvt.rna.tf32.f32 %0, %1;" : "=r"(r) : "f"(x)); return r;
}
__device__ __forceinline__ void mma8(float c[4],
    unsigned a0, unsigned a1, unsigned a2, unsigned a3, unsigned b0, unsigned b1) {
    asm volatile(
        "mma.sync.aligned.m16n8k8.row.col.f32.tf32.tf32.f32 "
        "{%0,%1,%2,%3},{%4,%5,%6,%7},{%8,%9},{%0,%1,%2,%3};"
        : "+f"(c[0]), "+f"(c[1]), "+f"(c[2]), "+f"(c[3])
        : "r"(a0), "r"(a1), "r"(a2), "r"(a3), "r"(b0), "r"(b1));
}
#define CPA(dst, src) asm volatile("cp.async.cg.shared.global [%0],[%1],16;\n" :: "r"(dst), "l"(src))
#define CPC()         asm volatile("cp.async.commit_group;\n")
#define CPW(n)        asm volatile("cp.async.wait_group %0;\n" :: "n"(n))

// ---------------- elementwise: round fp32 -> tf32 bits ----------------
__global__ void round_kernel(const float* __restrict__ in, unsigned* __restrict__ out, size_t n4) {
    for (size_t i = (size_t)blockIdx.x * blockDim.x + threadIdx.x; i < n4;
         i += (size_t)gridDim.x * blockDim.x) {
        float4 v = ((const float4*)in)[i];
        uint4 t = { f2tf(v.x), f2tf(v.y), f2tf(v.z), f2tf(v.w) };
        ((uint4*)out)[i] = t;
    }
}

// ---------------- concat -> tf32: cat_t = round([mem; inputs]) ----------------
__global__ void concat_tf32(const float* __restrict__ mem,
                            const float* __restrict__ inp,
                            unsigned* __restrict__ cat) {
    size_t n_mem4 = (size_t)MEMLEN * BATCH * DMODEL / 4;
    size_t n_tot4 = (size_t)KLEN   * BATCH * DMODEL / 4;
    for (size_t i = (size_t)blockIdx.x * blockDim.x + threadIdx.x; i < n_tot4;
         i += (size_t)gridDim.x * blockDim.x) {
        float4 v = (i < n_mem4) ? ((const float4*)mem)[i] : ((const float4*)inp)[i - n_mem4];
        uint4 t = { f2tf(v.x), f2tf(v.y), f2tf(v.z), f2tf(v.w) };
        ((uint4*)cat)[i] = t;
    }
}

// ---------------- addvec_round: out[i,b,:] = round(q[i,b,:] + vec[:]) ----------------
__global__ void addvec_round(const unsigned* __restrict__ qkv_t,
                             const float* __restrict__ vec,
                             unsigned* __restrict__ out) {
    size_t n4 = (size_t)QLEN * BATCH * DMODEL / 4;
    for (size_t i4 = (size_t)blockIdx.x * blockDim.x + threadIdx.x; i4 < n4;
         i4 += (size_t)gridDim.x * blockDim.x) {
        size_t idx = i4 * 4;
        int hd = (int)(idx & (DMODEL - 1));
        size_t ib = idx >> 10;                       // i*BATCH + b
        size_t src = ((size_t)MEMLEN * BATCH + ib) * QKV3 + hd;
        uint4 q = *(const uint4*)(qkv_t + src);
        float4 vv = *(const float4*)(vec + hd);
        uint4 t = { f2tf(__uint_as_float(q.x) + vv.x), f2tf(__uint_as_float(q.y) + vv.y),
                    f2tf(__uint_as_float(q.z) + vv.z), f2tf(__uint_as_float(q.w) + vv.w) };
        ((uint4*)out)[i4] = t;
    }
}

// ---------------- cp.async double-buffered tf32 GEMM ----------------
// C = A[M,K] @ B[K,N] (+bias)(+relu); output fp32 (Cf) or tf32 bits (Ct)
#define GAS 36
#define GBS 136
__global__ __launch_bounds__(256, 2) void gemm_tf32(
    const unsigned* __restrict__ A, const unsigned* __restrict__ B,
    float* __restrict__ Cf, unsigned* __restrict__ Ct,
    const float* __restrict__ bias, int M, int N, int K, int relu)
{
    extern __shared__ unsigned sm[];
    unsigned* As = sm;                   // [2][128*GAS]
    unsigned* Bs = sm + 2 * 128 * GAS;   // [2][32*GBS]
    unsigned sA = (unsigned)__cvta_generic_to_shared(As);
    unsigned sB = (unsigned)__cvta_generic_to_shared(Bs);
    int tid = threadIdx.x, lane = tid & 31, warp = tid >> 5;
    int qid = lane >> 2, qt = lane & 3;
    int wm = (warp >> 2) * 64, wn = (warp & 3) * 32;
    int m0 = blockIdx.y * 128, n0 = blockIdx.x * 128;

    float c[4][4][4];
    #pragma unroll
    for (int mi = 0; mi < 4; mi++)
        #pragma unroll
        for (int ni = 0; ni < 4; ni++)
            #pragma unroll
            for (int t = 0; t < 4; t++) c[mi][ni][t] = 0.0f;

    // preload stage 0 (full tiles: A 128x32 = 1024 uint4, B 32x128 = 1024 uint4)
    #pragma unroll
    for (int i = 0; i < 4; i++) {
        int id = tid + i * 256; int r = id >> 3, c4 = (id & 7) * 4;
        CPA(sA + (r * GAS + c4) * 4, A + (size_t)(m0 + r) * K + c4);
    }
    #pragma unroll
    for (int i = 0; i < 4; i++) {
        int id = tid + i * 256; int r = id >> 5, c4 = (id & 31) * 4;
        CPA(sB + (r * GBS + c4) * 4, B + (size_t)r * N + n0 + c4);
    }
    CPC();

    int KT = K >> 5;
    for (int kt = 0; kt < KT; kt++) {
        int s = kt & 1;
        if (kt + 1 < KT) {
            int k1 = (kt + 1) << 5;
            #pragma unroll
            for (int i = 0; i < 4; i++) {
                int id = tid + i * 256; int r = id >> 3, c4 = (id & 7) * 4;
                CPA(sA + ((s ^ 1) * 128 * GAS + r * GAS + c4) * 4,
                    A + (size_t)(m0 + r) * K + k1 + c4);
            }
            #pragma unroll
            for (int i = 0; i < 4; i++) {
                int id = tid + i * 256; int r = id >> 5, c4 = (id & 31) * 4;
                CPA(sB + ((s ^ 1) * 32 * GBS + r * GBS + c4) * 4,
                    B + (size_t)(k1 + r) * N + n0 + c4);
            }
        }
        CPC();
        CPW(1);
        __syncthreads();
        const unsigned* Asb = As + s * 128 * GAS;
        const unsigned* Bsb = Bs + s * 32 * GBS;
        #pragma unroll
        for (int kk = 0; kk < 4; kk++) {
            unsigned a[4][4], bf[4][2];
            #pragma unroll
            for (int mi = 0; mi < 4; mi++) {
                int base = (wm + mi * 16 + qid) * GAS + kk * 8 + qt;
                a[mi][0] = Asb[base];     a[mi][1] = Asb[base + 8 * GAS];
                a[mi][2] = Asb[base + 4]; a[mi][3] = Asb[base + 8 * GAS + 4];
            }
            #pragma unroll
            for (int ni = 0; ni < 4; ni++) {
                int base = (kk * 8 + qt) * GBS + wn + ni * 8 + qid;
                bf[ni][0] = Bsb[base]; bf[ni][1] = Bsb[base + 4 * GBS];
            }
            #pragma unroll
            for (int mi = 0; mi < 4; mi++)
                #pragma unroll
                for (int ni = 0; ni < 4; ni++)
                    mma8(c[mi][ni], a[mi][0], a[mi][1], a[mi][2], a[mi][3],
                         bf[ni][0], bf[ni][1]);
        }
        __syncthreads();
    }
    #pragma unroll
    for (int mi = 0; mi < 4; mi++) {
        int row = m0 + wm + mi * 16 + qid;
        #pragma unroll
        for (int ni = 0; ni < 4; ni++) {
            int col = n0 + wn + ni * 8 + qt * 2;
            float b0 = bias ? bias[col] : 0.0f;
            float b1 = bias ? bias[col + 1] : 0.0f;
            float v00 = c[mi][ni][0] + b0, v01 = c[mi][ni][1] + b1;
            float v10 = c[mi][ni][2] + b0, v11 = c[mi][ni][3] + b1;
            if (relu) { v00 = fmaxf(v00, 0.f); v01 = fmaxf(v01, 0.f);
                        v10 = fmaxf(v10, 0.f); v11 = fmaxf(v11, 0.f); }
            if (Ct) {
                Ct[(size_t)row * N + col]           = f2tf(v00);
                Ct[(size_t)row * N + col + 1]       = f2tf(v01);
                Ct[(size_t)(row + 8) * N + col]     = f2tf(v10);
                Ct[(size_t)(row + 8) * N + col + 1] = f2tf(v11);
            } else {
                Cf[(size_t)row * N + col]           = v00;
                Cf[(size_t)row * N + col + 1]       = v01;
                Cf[(size_t)(row + 8) * N + col]     = v10;
                Cf[(size_t)(row + 8) * N + col + 1] = v11;
            }
        }
    }
}

// ---------------- BD kernel: scatter-store pre-shifted scaled BD ----------------
// BDraw[i,j'] = (q_i+v_h) . rp[j'] ; store BDs[i, j'-(Q-1)+i] = SCALE*BDraw
#define BDS 68
__global__ __launch_bounds__(256) void bd_tf32(
    const unsigned* __restrict__ qv, const unsigned* __restrict__ rp,
    float* __restrict__ BDs)
{
    int i0 = blockIdx.y * 128, j0 = blockIdx.x * 128;
    if (j0 + i0 <= QLEN - 256) return;   // all stored j < 0: tile dead
    extern __shared__ unsigned sm[];
    unsigned* Qs = sm;                 // [128][BDS]
    unsigned* Rs = sm + 128 * BDS;     // [128][BDS]
    int tid = threadIdx.x, lane = tid & 31, warp = tid >> 5;
    int qid = lane >> 2, qt = lane & 3;
    int wm = (warp >> 2) * 64, wn = (warp & 3) * 32;
    int bh = blockIdx.z, b = bh >> 4, h = bh & 15;

    #pragma unroll
    for (int i = 0; i < 8; i++) {
        int id = tid + i * 256; int r = id >> 4, c4 = (id & 15) * 4;
        *(uint4*)&Qs[r * BDS + c4] =
            *(const uint4*)(qv + ((size_t)(i0 + r) * BATCH + b) * DMODEL + h * 64 + c4);
        *(uint4*)&Rs[r * BDS + c4] =
            *(const uint4*)(rp + (size_t)(j0 + r) * DMODEL + h * 64 + c4);
    }
    __syncthreads();
    float c[4][4][4];
    #pragma unroll
    for (int mi = 0; mi < 4; mi++)
        #pragma unroll
        for (int ni = 0; ni < 4; ni++)
            #pragma unroll
            for (int t = 0; t < 4; t++) c[mi][ni][t] = 0.0f;
    #pragma unroll
    for (int kk = 0; kk < 8; kk++) {
        unsigned a[4][4], bf[4][2];
        #pragma unroll
        for (int mi = 0; mi < 4; mi++) {
            int base = (wm + mi * 16 + qid) * BDS + kk * 8 + qt;
            a[mi][0] = Qs[base];     a[mi][1] = Qs[base + 8 * BDS];
            a[mi][2] = Qs[base + 4]; a[mi][3] = Qs[base + 8 * BDS + 4];
        }
        #pragma unroll
        for (int ni = 0; ni < 4; ni++) {
            int base = (wn + ni * 8 + qid) * BDS + kk * 8 + qt;
            bf[ni][0] = Rs[base]; bf[ni][1] = Rs[base + 4];
        }
        #pragma unroll
        for (int mi = 0; mi < 4; mi++)
            #pragma unroll
            for (int ni = 0; ni < 4; ni++)
                mma8(c[mi][ni], a[mi][0], a[mi][1], a[mi][2], a[mi][3],
                     bf[ni][0], bf[ni][1]);
    }
    float* bdp = BDs + (size_t)bh * QLEN * KLEN;
    #pragma unroll
    for (int mi = 0; mi < 4; mi++) {
        #pragma unroll
        for (int half = 0; half < 2; half++) {
            int i = i0 + wm + mi * 16 + qid + half * 8;
            int jbase = j0 - (QLEN - 1) + i;
            #pragma unroll
            for (int ni = 0; ni < 4; ni++) {
                int j = jbase + wn + ni * 8 + qt * 2;
                float v0 = c[mi][ni][half * 2] * ATT_SCALE;
                float v1 = c[mi][ni][half * 2 + 1] * ATT_SCALE;
                if (j >= 0 && j < KLEN)         bdp[(size_t)i * KLEN + j]     = v0;
                if (j + 1 >= 0 && j + 1 < KLEN) bdp[(size_t)i * KLEN + j + 1] = v1;
            }
        }
    }
}

// ---------------- fused flash attention ----------------
// per (bh, i-tile 128): S = SCALE*(q+u)K^T + BDs ; online softmax (cross-warp) ; O += P V
#define FQS 68
#define FVS 72
#define FPS 132
__global__ __launch_bounds__(256) void flash_attn(
    const unsigned* __restrict__ qu, const unsigned* __restrict__ qkv_t,
    const float* __restrict__ BDs, unsigned* __restrict__ ctx_t)
{
    extern __shared__ unsigned sm[];
    unsigned* Qs = sm;                               // [128][FQS]
    unsigned* Ks = Qs + 128 * FQS;                   // [128][FQS]
    unsigned* Vs = Ks + 128 * FQS;                   // [128][FVS]  ([j][d])
    unsigned* Ps = Vs + 128 * FVS;                   // [128][FPS]
    unsigned sK = (unsigned)__cvta_generic_to_shared(Ks);
    unsigned sV = (unsigned)__cvta_generic_to_shared(Vs);
    __shared__ float redm[4][128];
    __shared__ float reds[4][128];

    int tid = threadIdx.x, lane = tid & 31, warp = tid >> 5;
    int qid = lane >> 2, qt = lane & 3;
    int wm = (warp >> 2) * 64, wn = (warp & 3) * 32;  // S: 2m x 4n
    int wno = (warp & 3) * 16;                        // O: cols per warp
    int wcol = warp & 3;
    int bh = blockIdx.y, b = bh >> 4, h = bh & 15;
    int i0 = blockIdx.x * 128;

    // load Q tile once (128x64)
    #pragma unroll
    for (int i = 0; i < 8; i++) {
        int id = tid + i * 256; int r = id >> 4, c4 = (id & 15) * 4;
        *(uint4*)&Qs[r * FQS + c4] =
            *(const uint4*)(qu + ((size_t)(i0 + r) * BATCH + b) * DMODEL + h * 64 + c4);
    }

    float m[8], l[8], alpha[8], co[4][2][4];
    #pragma unroll
    for (int i = 0; i < 8; i++) { m[i] = -1e30f; l[i] = 0.0f; }
    #pragma unroll
    for (int mi = 0; mi < 4; mi++)
        #pragma unroll
        for (int ni = 0; ni < 2; ni++)
            #pragma unroll
            for (int t = 0; t < 4; t++) co[mi][ni][t] = 0.0f;

    const float* bdp = BDs + ((size_t)bh * QLEN + i0) * KLEN;
    int njt = (i0 + 127 + MEMLEN) / 128 + 1;
    if (njt > KLEN / 128) njt = KLEN / 128;

    for (int jt = 0; jt < njt; jt++) {
        int j0 = jt * 128;
        // async load K and V tiles (128x64 each)
        #pragma unroll
        for (int i = 0; i < 8; i++) {
            int id = tid + i * 256; int r = id >> 4, c4 = (id & 15) * 4;
            const unsigned* kg = qkv_t + ((size_t)(j0 + r) * BATCH + b) * QKV3 + DMODEL + h * 64 + c4;
            CPA(sK + (r * FQS + c4) * 4, kg);
            CPA(sV + (r * FVS + c4) * 4, kg + DMODEL);
        }
        CPC();
        CPW(0);
        __syncthreads();

        // S = Q K^T
        float cs[4][4][4];
        #pragma unroll
        for (int mi = 0; mi < 4; mi++)
            #pragma unroll
            for (int ni = 0; ni < 4; ni++)
                #pragma unroll
                for (int t = 0; t < 4; t++) cs[mi][ni][t] = 0.0f;
        #pragma unroll
        for (int kk = 0; kk < 8; kk++) {
            unsigned a[4][4], bf[4][2];
            #pragma unroll
            for (int mi = 0; mi < 4; mi++) {
                int base = (wm + mi * 16 + qid) * FQS + kk * 8 + qt;
                a[mi][0] = Qs[base];     a[mi][1] = Qs[base + 8 * FQS];
                a[mi][2] = Qs[base + 4]; a[mi][3] = Qs[base + 8 * FQS + 4];
            }
            #pragma unroll
            for (int ni = 0; ni < 4; ni++) {
                int base = (wn + ni * 8 + qid) * FQS + kk * 8 + qt;
                bf[ni][0] = Ks[base]; bf[ni][1] = Ks[base + 4];
            }
            #pragma unroll
            for (int mi = 0; mi < 4; mi++)
                #pragma unroll
                for (int ni = 0; ni < 4; ni++)
                    mma8(cs[mi][ni], a[mi][0], a[mi][1], a[mi][2], a[mi][3],
                         bf[ni][0], bf[ni][1]);
        }

        // phase A: scale + BD + mask, warp-local row max -> redm
        int need_mask = (j0 + 127 > i0 + MEMLEN);
        #pragma unroll
        for (int mi = 0; mi < 4; mi++) {
            #pragma unroll
            for (int half = 0; half < 2; half++) {
                int rloc = wm + mi * 16 + qid + half * 8;
                int i = i0 + rloc;
                float tmax = -1e30f;
                #pragma unroll
                for (int ni = 0; ni < 4; ni++) {
                    int j = j0 + wn + ni * 8 + qt * 2;
                    float2 bd = *(const float2*)(bdp + (size_t)rloc * KLEN + j);
                    float s0 = cs[mi][ni][half * 2]     * ATT_SCALE + bd.x;
                    float s1 = cs[mi][ni][half * 2 + 1] * ATT_SCALE + bd.y;
                    if (need_mask) {
                        if (j     > i + MEMLEN) s0 = -1e30f;
                        if (j + 1 > i + MEMLEN) s1 = -1e30f;
                    }
                    cs[mi][ni][half * 2]     = s0;
                    cs[mi][ni][half * 2 + 1] = s1;
                    tmax = fmaxf(tmax, fmaxf(s0, s1));
                }
                tmax = fmaxf(tmax, __shfl_xor_sync(0xffffffffu, tmax, 1));
                tmax = fmaxf(tmax, __shfl_xor_sync(0xffffffffu, tmax, 2));
                if (qt == 0) redm[wcol][rloc] = tmax;
            }
        }
        __syncthreads();

        // phase B: global max, alpha, P=exp, warp rowsum -> reds
        #pragma unroll
        for (int mi = 0; mi < 4; mi++) {
            #pragma unroll
            for (int half = 0; half < 2; half++) {
                int rw = mi * 2 + half;
                int rloc = wm + mi * 16 + qid + half * 8;
                float tg = fmaxf(fmaxf(redm[0][rloc], redm[1][rloc]),
                                 fmaxf(redm[2][rloc], redm[3][rloc]));
                float mn = fmaxf(m[rw], tg);
                float al = __expf(m[rw] - mn);
                m[rw] = mn; alpha[rw] = al;
                #pragma unroll
                for (int ni = 0; ni < 2; ni++) {
                    co[mi][ni][half * 2]     *= al;
                    co[mi][ni][half * 2 + 1] *= al;
                }
                float rowsum = 0.0f;
                #pragma unroll
                for (int ni = 0; ni < 4; ni++) {
                    float p0 = __expf(cs[mi][ni][half * 2]     - mn);
                    float p1 = __expf(cs[mi][ni][half * 2 + 1] - mn);
                    rowsum += p0 + p1;
                    int col = wn + ni * 8 + qt * 2;
                    Ps[rloc * FPS + col]     = f2tf(p0);
                    Ps[rloc * FPS + col + 1] = f2tf(p1);
                }
                rowsum += __shfl_xor_sync(0xffffffffu, rowsum, 1);
                rowsum += __shfl_xor_sync(0xffffffffu, rowsum, 2);
                if (qt == 0) reds[wcol][rloc] = rowsum;
            }
        }
        __syncthreads();

        // phase C: combine rowsums, update l
        #pragma unroll
        for (int mi = 0; mi < 4; mi++) {
            #pragma unroll
            for (int half = 0; half < 2; half++) {
                int rw = mi * 2 + half;
                int rloc = wm + mi * 16 + qid + half * 8;
                float rs = reds[0][rloc] + reds[1][rloc] + reds[2][rloc] + reds[3][rloc];
                l[rw] = l[rw] * alpha[rw] + rs;
            }
        }

        // O += P @ V
        #pragma unroll
        for (int kk = 0; kk < 16; kk++) {
            unsigned a[4][4], bf[2][2];
            #pragma unroll
            for (int mi = 0; mi < 4; mi++) {
                int base = (wm + mi * 16 + qid) * FPS + kk * 8 + qt;
                a[mi][0] = Ps[base];     a[mi][1] = Ps[base + 8 * FPS];
                a[mi][2] = Ps[base + 4]; a[mi][3] = Ps[base + 8 * FPS + 4];
            }
            #pragma unroll
            for (int ni = 0; ni < 2; ni++) {
                int base = (kk * 8 + qt) * FVS + wno + ni * 8 + qid;
                bf[ni][0] = Vs[base]; bf[ni][1] = Vs[base + 4 * FVS];
            }
            #pragma unroll
            for (int mi = 0; mi < 4; mi++)
                #pragma unroll
                for (int ni = 0; ni < 2; ni++)
                    mma8(co[mi][ni], a[mi][0], a[mi][1], a[mi][2], a[mi][3],
                         bf[ni][0], bf[ni][1]);
        }
        __syncthreads();
    }
    // epilogue: O /= l, write tf32 ctx
    #pragma unroll
    for (int mi = 0; mi < 4; mi++) {
        #pragma unroll
        for (int half = 0; half < 2; half++) {
            int rw = mi * 2 + half;
            float inv = 1.0f / l[rw];
            int row = i0 + wm + mi * 16 + qid + half * 8;
            #pragma unroll
            for (int ni = 0; ni < 2; ni++) {
                int col = wno + ni * 8 + qt * 2;
                unsigned* p = ctx_t + ((size_t)row * BATCH + b) * DMODEL + h * 64 + col;
                p[0] = f2tf(co[mi][ni][half * 2] * inv);
                p[1] = f2tf(co[mi][ni][half * 2 + 1] * inv);
            }
        }
    }
}

// ---------------- layernorm: out = LN(a + b) * g + beta (+ optional tf32 copy) ----------------
__global__ __launch_bounds__(256) void ln_kernel(
    const float* __restrict__ a, const float* __restrict__ bres,
    const float* __restrict__ g, const float* __restrict__ beta,
    float* __restrict__ out, unsigned* __restrict__ out_t)
{
    int row = blockIdx.x;
    int tid = threadIdx.x;
    const float* ap = a    + (size_t)row * DMODEL;
    const float* bp = bres + (size_t)row * DMODEL;
    float x[4];
    float sum = 0.0f;
    #pragma unroll
    for (int t = 0; t < 4; t++) {
        int c = tid + t * 256;
        x[t] = ap[c] + bp[c];
        sum += x[t];
    }
    __shared__ float red[256];
    red[tid] = sum; __syncthreads();
    for (int o = 128; o > 0; o >>= 1) {
        if (tid < o) red[tid] += red[tid + o];
        __syncthreads();
    }
    float mean = red[0] * (1.0f / DMODEL); __syncthreads();
    float vs = 0.0f;
    #pragma unroll
    for (int t = 0; t < 4; t++) { float d = x[t] - mean; vs += d * d; }
    red[tid] = vs; __syncthreads();
    for (int o = 128; o > 0; o >>= 1) {
        if (tid < o) red[tid] += red[tid + o];
        __syncthreads();
    }
    float inv = rsqrtf(red[0] * (1.0f / DMODEL) + LNEPS);
    #pragma unroll
    for (int t = 0; t < 4; t++) {
        int c = tid + t * 256;
        float v = (x[t] - mean) * inv * g[c] + beta[c];
        out[(size_t)row * DMODEL + c] = v;
        if (out_t) out_t[(size_t)row * DMODEL + c] = f2tf(v);
    }
}

// ---------------- launch ----------------
extern "C" void kernel_launch(void* const* d_in, const int* in_sizes, int n_in,
                              void* d_out, int out_size)
{
    const float* inputs = (const float*)d_in[0];
    const float* r      = (const float*)d_in[1];
    const float* u      = (const float*)d_in[2];
    const float* v      = (const float*)d_in[3];
    const float* mem    = (const float*)d_in[4];
    const float* W_qkv  = (const float*)d_in[6];
    const float* W_r    = (const float*)d_in[7];
    const float* W_o    = (const float*)d_in[8];
    const float* ln1_g  = (const float*)d_in[9];
    const float* ln1_b  = (const float*)d_in[10];
    const float* ln2_g  = (const float*)d_in[11];
    const float* ln2_b  = (const float*)d_in[12];
    const float* W1     = (const float*)d_in[13];
    const float* b1     = (const float*)d_in[14];
    const float* W2     = (const float*)d_in[15];
    const float* b2     = (const float*)d_in[16];
    float* out = (float*)d_out;

    unsigned *cat_t, *qkv_t, *rp_t, *qu, *qv, *ctx_t, *x_t, *h_t;
    unsigned *wqkv_t, *wr_t, *wo_t, *w1_t, *w2_t, *r_t;
    float *BDs, *y, *x, *y2;
    cudaGetSymbolAddress((void**)&cat_t,  g_cat_t);
    cudaGetSymbolAddress((void**)&qkv_t,  g_qkv_t);
    cudaGetSymbolAddress((void**)&rp_t,   g_rp_t);
    cudaGetSymbolAddress((void**)&qu,     g_qu);
    cudaGetSymbolAddress((void**)&qv,     g_qv);
    cudaGetSymbolAddress((void**)&BDs,    g_BD);
    cudaGetSymbolAddress((void**)&ctx_t,  g_ctx_t);
    cudaGetSymbolAddress((void**)&y,      g_y);
    cudaGetSymbolAddress((void**)&x,      g_x);
    cudaGetSymbolAddress((void**)&x_t,    g_x_t);
    cudaGetSymbolAddress((void**)&h_t,    g_h_t);
    cudaGetSymbolAddress((void**)&y2,     g_y2);
    cudaGetSymbolAddress((void**)&wqkv_t, g_wqkv_t);
    cudaGetSymbolAddress((void**)&wr_t,   g_wr_t);
    cudaGetSymbolAddress((void**)&wo_t,   g_wo_t);
    cudaGetSymbolAddress((void**)&w1_t,   g_w1_t);
    cudaGetSymbolAddress((void**)&w2_t,   g_w2_t);
    cudaGetSymbolAddress((void**)&r_t,    g_r_t);

    const int gemm_smem  = (2 * 128 * GAS + 2 * 32 * GBS) * 4;
    const int bd_smem    = (2 * 128 * BDS) * 4;
    const int flash_smem = (128 * FQS * 2 + 128 * FVS + 128 * FPS) * 4;
    cudaFuncSetAttribute(gemm_tf32,  cudaFuncAttributeMaxDynamicSharedMemorySize, gemm_smem);
    cudaFuncSetAttribute(bd_tf32,    cudaFuncAttributeMaxDynamicSharedMemorySize, bd_smem);
    cudaFuncSetAttribute(flash_attn, cudaFuncAttributeMaxDynamicSharedMemorySize, flash_smem);

    // 0. round weights + r to tf32 bit patterns
    round_kernel<<<1024, 256>>>(W_qkv, wqkv_t, (size_t)DMODEL * QKV3 / 4);
    round_kernel<<<512,  256>>>(W_r,   wr_t,   (size_t)DMODEL * DMODEL / 4);
    round_kernel<<<512,  256>>>(W_o,   wo_t,   (size_t)DMODEL * DMODEL / 4);
    round_kernel<<<1024, 256>>>(W1,    w1_t,   (size_t)DMODEL * MLPD / 4);
    round_kernel<<<1024, 256>>>(W2,    w2_t,   (size_t)MLPD * DMODEL / 4);
    round_kernel<<<512,  256>>>(r,     r_t,    (size_t)KLEN * DMODEL / 4);

    // 1. cat_t = round([mem; inputs])
    concat_tf32<<<2048, 256>>>(mem, inputs, cat_t);

    // 2. qkv_t = cat_t @ W_qkv (tf32 out)
    gemm_tf32<<<dim3(QKV3 / 128, (KLEN * BATCH) / 128), 256, gemm_smem>>>(
        cat_t, wqkv_t, nullptr, qkv_t, nullptr, KLEN * BATCH, QKV3, DMODEL, 0);

    // 3. rp_t = r @ W_r (tf32 out)
    gemm_tf32<<<dim3(DMODEL / 128, KLEN / 128), 256, gemm_smem>>>(
        r_t, wr_t, nullptr, rp_t, nullptr, KLEN, DMODEL, DMODEL, 0);

    // 4. qu = round(q + u), qv = round(q + v)
    addvec_round<<<1024, 256>>>(qkv_t, u, qu);
    addvec_round<<<1024, 256>>>(qkv_t, v, qv);

    // 5. BDs (pre-shifted, pre-scaled)
    bd_tf32<<<dim3(KLEN / 128, QLEN / 128, BATCH * NH), 256, bd_smem>>>(qv, rp_t, BDs);

    // 6. fused flash attention -> ctx_t
    flash_attn<<<dim3(QLEN / 128, BATCH * NH), 256, flash_smem>>>(qu, qkv_t, BDs, ctx_t);

    // 7. y = ctx_t @ W_o (fp32 out)
    gemm_tf32<<<dim3(DMODEL / 128, (QLEN * BATCH) / 128), 256, gemm_smem>>>(
        ctx_t, wo_t, y, nullptr, nullptr, QLEN * BATCH, DMODEL, DMODEL, 0);

    // 8. x = LN1(inputs + y)  (+ tf32 copy)
    ln_kernel<<<QLEN * BATCH, 256>>>(inputs, y, ln1_g, ln1_b, x, x_t);

    // 9. h_t = relu(x_t @ W1 + b1) (tf32 out)
    gemm_tf32<<<dim3(MLPD / 128, (QLEN * BATCH) / 128), 256, gemm_smem>>>(
        x_t, w1_t, nullptr, h_t, b1, QLEN * BATCH, MLPD, DMODEL, 1);

    // 10. y2 = h_t @ W2 + b2 (fp32 out)
    gemm_tf32<<<dim3(DMODEL / 128, (QLEN * BATCH) / 128), 256, gemm_smem>>>(
        h_t, w2_t, y2, nullptr, b2, QLEN * BATCH, DMODEL, MLPD, 0);

    // 11. out = LN2(x + y2)
    ln_kernel<<<QLEN * BATCH, 256>>>(x, y2, ln2_g, ln2_b, out, nullptr);
}

// round 6
// speedup vs baseline: 4.5881x; 1.0151x over previous
#include <cuda_runtime.h>
#include <math.h>

#define QLEN  1024
#define BATCH 4
#define DMODEL 1024
#define NH    16
#define HD    64
#define MEMLEN 512
#define KLEN  1536
#define MLPD  4096
#define QKV3  3072
#define ATT_SCALE 0.125f
#define LNEPS 1e-5f

// ---------------- scratch (static device globals; no allocation) ----------------
__device__ unsigned g_cat_t [(size_t)KLEN * BATCH * DMODEL];
__device__ unsigned g_qkv_t [(size_t)KLEN * BATCH * QKV3];
__device__ unsigned g_rp_t  [(size_t)KLEN * DMODEL];
__device__ float    g_BD    [(size_t)BATCH * NH * QLEN * KLEN];   // pre-shifted, pre-scaled
__device__ unsigned g_ctx_t [(size_t)QLEN * BATCH * DMODEL];
__device__ float    g_y     [(size_t)QLEN * BATCH * DMODEL];
__device__ float    g_x     [(size_t)QLEN * BATCH * DMODEL];
__device__ unsigned g_x_t   [(size_t)QLEN * BATCH * DMODEL];
__device__ unsigned g_h_t   [(size_t)QLEN * BATCH * MLPD];
__device__ float    g_y2    [(size_t)QLEN * BATCH * DMODEL];
__device__ unsigned g_wqkv_t[(size_t)DMODEL * QKV3];
__device__ unsigned g_wr_t  [(size_t)DMODEL * DMODEL];
__device__ unsigned g_wo_t  [(size_t)DMODEL * DMODEL];
__device__ unsigned g_w1_t  [(size_t)DMODEL * MLPD];
__device__ unsigned g_w2_t  [(size_t)MLPD * DMODEL];
__device__ unsigned g_r_t   [(size_t)KLEN * DMODEL];

// ---------------- helpers ----------------
__device__ __forceinline__ unsigned f2tf(float x) {
    unsigned r; asm("cvt.rna.tf32.f32 %0, %1;" : "=r"(r) : "f"(x)); return r;
}
__device__ __forceinline__ void mma8(float c[4],
    unsigned a0, unsigned a1, unsigned a2, unsigned a3, unsigned b0, unsigned b1) {
    asm volatile(
        "mma.sync.aligned.m16n8k8.row.col.f32.tf32.tf32.f32 "
        "{%0,%1,%2,%3},{%4,%5,%6,%7},{%8,%9},{%0,%1,%2,%3};"
        : "+f"(c[0]), "+f"(c[1]), "+f"(c[2]), "+f"(c[3])
        : "r"(a0), "r"(a1), "r"(a2), "r"(a3), "r"(b0), "r"(b1));
}
#define CPA(dst, src) asm volatile("cp.async.cg.shared.global [%0],[%1],16;\n" :: "r"(dst), "l"(src))
#define CPC()         asm volatile("cp.async.commit_group;\n")
#define CPW(n)        asm volatile("cp.async.wait_group %0;\n" :: "n"(n))

// ---------------- elementwise: round fp32 -> tf32 bits ----------------
__global__ void round_kernel(const float* __restrict__ in, unsigned* __restrict__ out, size_t n4) {
    for (size_t i = (size_t)blockIdx.x * blockDim.x + threadIdx.x; i < n4;
         i += (size_t)gridDim.x * blockDim.x) {
        float4 v = ((const float4*)in)[i];
        uint4 t = { f2tf(v.x), f2tf(v.y), f2tf(v.z), f2tf(v.w) };
        ((uint4*)out)[i] = t;
    }
}

// ---------------- concat -> tf32: cat_t = round([mem; inputs]) ----------------
__global__ void concat_tf32(const float* __restrict__ mem,
                            const float* __restrict__ inp,
                            unsigned* __restrict__ cat) {
    size_t n_mem4 = (size_t)MEMLEN * BATCH * DMODEL / 4;
    size_t n_tot4 = (size_t)KLEN   * BATCH * DMODEL / 4;
    for (size_t i = (size_t)blockIdx.x * blockDim.x + threadIdx.x; i < n_tot4;
         i += (size_t)gridDim.x * blockDim.x) {
        float4 v = (i < n_mem4) ? ((const float4*)mem)[i] : ((const float4*)inp)[i - n_mem4];
        uint4 t = { f2tf(v.x), f2tf(v.y), f2tf(v.z), f2tf(v.w) };
        ((uint4*)cat)[i] = t;
    }
}

// ---------------- cp.async double-buffered tf32 GEMM ----------------
// C = A[M,K] @ B[K,N] (+bias)(+relu); output fp32 (Cf) or tf32 bits (Ct)
#define GAS 36
#define GBS 136
__global__ __launch_bounds__(256, 2) void gemm_tf32(
    const unsigned* __restrict__ A, const unsigned* __restrict__ B,
    float* __restrict__ Cf, unsigned* __restrict__ Ct,
    const float* __restrict__ bias, int M, int N, int K, int relu, int qkvskip)
{
    extern __shared__ unsigned sm[];
    unsigned* As = sm;                   // [2][128*GAS]
    unsigned* Bs = sm + 2 * 128 * GAS;   // [2][32*GBS]
    unsigned sA = (unsigned)__cvta_generic_to_shared(As);
    unsigned sB = (unsigned)__cvta_generic_to_shared(Bs);
    int tid = threadIdx.x, lane = tid & 31, warp = tid >> 5;
    int qid = lane >> 2, qt = lane & 3;
    int wm = (warp >> 2) * 64, wn = (warp & 3) * 32;
    int m0 = blockIdx.y * 128, n0 = blockIdx.x * 128;
    // qkv GEMM: mem rows (< MEMLEN*BATCH) never need the Q third (cols < DMODEL)
    if (qkvskip && (m0 + 128 <= MEMLEN * BATCH) && (n0 < DMODEL)) return;

    float c[4][4][4];
    #pragma unroll
    for (int mi = 0; mi < 4; mi++)
        #pragma unroll
        for (int ni = 0; ni < 4; ni++)
            #pragma unroll
            for (int t = 0; t < 4; t++) c[mi][ni][t] = 0.0f;

    // preload stage 0
    #pragma unroll
    for (int i = 0; i < 4; i++) {
        int id = tid + i * 256; int r = id >> 3, c4 = (id & 7) * 4;
        CPA(sA + (r * GAS + c4) * 4, A + (size_t)(m0 + r) * K + c4);
    }
    #pragma unroll
    for (int i = 0; i < 4; i++) {
        int id = tid + i * 256; int r = id >> 5, c4 = (id & 31) * 4;
        CPA(sB + (r * GBS + c4) * 4, B + (size_t)r * N + n0 + c4);
    }
    CPC();

    int KT = K >> 5;
    for (int kt = 0; kt < KT; kt++) {
        int s = kt & 1;
        if (kt + 1 < KT) {
            int k1 = (kt + 1) << 5;
            #pragma unroll
            for (int i = 0; i < 4; i++) {
                int id = tid + i * 256; int r = id >> 3, c4 = (id & 7) * 4;
                CPA(sA + ((s ^ 1) * 128 * GAS + r * GAS + c4) * 4,
                    A + (size_t)(m0 + r) * K + k1 + c4);
            }
            #pragma unroll
            for (int i = 0; i < 4; i++) {
                int id = tid + i * 256; int r = id >> 5, c4 = (id & 31) * 4;
                CPA(sB + ((s ^ 1) * 32 * GBS + r * GBS + c4) * 4,
                    B + (size_t)(k1 + r) * N + n0 + c4);
            }
        }
        CPC();
        CPW(1);
        __syncthreads();
        const unsigned* Asb = As + s * 128 * GAS;
        const unsigned* Bsb = Bs + s * 32 * GBS;
        #pragma unroll
        for (int kk = 0; kk < 4; kk++) {
            unsigned a[4][4], bf[4][2];
            #pragma unroll
            for (int mi = 0; mi < 4; mi++) {
                int base = (wm + mi * 16 + qid) * GAS + kk * 8 + qt;
                a[mi][0] = Asb[base];     a[mi][1] = Asb[base + 8 * GAS];
                a[mi][2] = Asb[base + 4]; a[mi][3] = Asb[base + 8 * GAS + 4];
            }
            #pragma unroll
            for (int ni = 0; ni < 4; ni++) {
                int base = (kk * 8 + qt) * GBS + wn + ni * 8 + qid;
                bf[ni][0] = Bsb[base]; bf[ni][1] = Bsb[base + 4 * GBS];
            }
            #pragma unroll
            for (int mi = 0; mi < 4; mi++)
                #pragma unroll
                for (int ni = 0; ni < 4; ni++)
                    mma8(c[mi][ni], a[mi][0], a[mi][1], a[mi][2], a[mi][3],
                         bf[ni][0], bf[ni][1]);
        }
        __syncthreads();
    }
    #pragma unroll
    for (int mi = 0; mi < 4; mi++) {
        int row = m0 + wm + mi * 16 + qid;
        #pragma unroll
        for (int ni = 0; ni < 4; ni++) {
            int col = n0 + wn + ni * 8 + qt * 2;
            float b0 = bias ? bias[col] : 0.0f;
            float b1 = bias ? bias[col + 1] : 0.0f;
            float v00 = c[mi][ni][0] + b0, v01 = c[mi][ni][1] + b1;
            float v10 = c[mi][ni][2] + b0, v11 = c[mi][ni][3] + b1;
            if (relu) { v00 = fmaxf(v00, 0.f); v01 = fmaxf(v01, 0.f);
                        v10 = fmaxf(v10, 0.f); v11 = fmaxf(v11, 0.f); }
            if (Ct) {
                Ct[(size_t)row * N + col]           = f2tf(v00);
                Ct[(size_t)row * N + col + 1]       = f2tf(v01);
                Ct[(size_t)(row + 8) * N + col]     = f2tf(v10);
                Ct[(size_t)(row + 8) * N + col + 1] = f2tf(v11);
            } else {
                Cf[(size_t)row * N + col]           = v00;
                Cf[(size_t)row * N + col + 1]       = v01;
                Cf[(size_t)(row + 8) * N + col]     = v10;
                Cf[(size_t)(row + 8) * N + col + 1] = v11;
            }
        }
    }
}

// ---------------- BD kernel: scatter-store pre-shifted scaled BD (v-add fused) ----------------
#define BDS 68
__global__ __launch_bounds__(256) void bd_tf32(
    const unsigned* __restrict__ qkv_t, const unsigned* __restrict__ rp,
    const float* __restrict__ vvec, float* __restrict__ BDs)
{
    int i0 = blockIdx.y * 128, j0 = blockIdx.x * 128;
    if (j0 + i0 <= QLEN - 256) return;   // all stored j < 0: tile dead
    extern __shared__ unsigned sm[];
    unsigned* Qs = sm;                 // [128][BDS]
    unsigned* Rs = sm + 128 * BDS;     // [128][BDS]
    int tid = threadIdx.x, lane = tid & 31, warp = tid >> 5;
    int qid = lane >> 2, qt = lane & 3;
    int wm = (warp >> 2) * 64, wn = (warp & 3) * 32;
    int bh = blockIdx.z, b = bh >> 4, h = bh & 15;

    #pragma unroll
    for (int i = 0; i < 8; i++) {
        int id = tid + i * 256; int r = id >> 4, c4 = (id & 15) * 4;
        uint4 q = *(const uint4*)(qkv_t + ((size_t)(MEMLEN + i0 + r) * BATCH + b) * QKV3 + h * 64 + c4);
        float4 vv = *(const float4*)(vvec + h * 64 + c4);
        uint4 t = { f2tf(__uint_as_float(q.x) + vv.x), f2tf(__uint_as_float(q.y) + vv.y),
                    f2tf(__uint_as_float(q.z) + vv.z), f2tf(__uint_as_float(q.w) + vv.w) };
        *(uint4*)&Qs[r * BDS + c4] = t;
        *(uint4*)&Rs[r * BDS + c4] =
            *(const uint4*)(rp + (size_t)(j0 + r) * DMODEL + h * 64 + c4);
    }
    __syncthreads();
    float c[4][4][4];
    #pragma unroll
    for (int mi = 0; mi < 4; mi++)
        #pragma unroll
        for (int ni = 0; ni < 4; ni++)
            #pragma unroll
            for (int t = 0; t < 4; t++) c[mi][ni][t] = 0.0f;
    #pragma unroll
    for (int kk = 0; kk < 8; kk++) {
        unsigned a[4][4], bf[4][2];
        #pragma unroll
        for (int mi = 0; mi < 4; mi++) {
            int base = (wm + mi * 16 + qid) * BDS + kk * 8 + qt;
            a[mi][0] = Qs[base];     a[mi][1] = Qs[base + 8 * BDS];
            a[mi][2] = Qs[base + 4]; a[mi][3] = Qs[base + 8 * BDS + 4];
        }
        #pragma unroll
        for (int ni = 0; ni < 4; ni++) {
            int base = (wn + ni * 8 + qid) * BDS + kk * 8 + qt;
            bf[ni][0] = Rs[base]; bf[ni][1] = Rs[base + 4];
        }
        #pragma unroll
        for (int mi = 0; mi < 4; mi++)
            #pragma unroll
            for (int ni = 0; ni < 4; ni++)
                mma8(c[mi][ni], a[mi][0], a[mi][1], a[mi][2], a[mi][3],
                     bf[ni][0], bf[ni][1]);
    }
    float* bdp = BDs + (size_t)bh * QLEN * KLEN;
    #pragma unroll
    for (int mi = 0; mi < 4; mi++) {
        #pragma unroll
        for (int half = 0; half < 2; half++) {
            int i = i0 + wm + mi * 16 + qid + half * 8;
            int jbase = j0 - (QLEN - 1) + i;
            #pragma unroll
            for (int ni = 0; ni < 4; ni++) {
                int j = jbase + wn + ni * 8 + qt * 2;
                float v0 = c[mi][ni][half * 2] * ATT_SCALE;
                float v1 = c[mi][ni][half * 2 + 1] * ATT_SCALE;
                if (j >= 0 && j < KLEN)         bdp[(size_t)i * KLEN + j]     = v0;
                if (j + 1 >= 0 && j + 1 < KLEN) bdp[(size_t)i * KLEN + j + 1] = v1;
            }
        }
    }
}

// ---------------- fused flash attention (row-per-warp, P in registers) ----------------
// Key-permutation trick: K tile rows stored permuted within 8-groups by
// kappa(w) = (w>>1) + 4*(w&1) so the S accumulator fragment IS the A-fragment for P@V.
#define FQS 68
#define FKS 68
#define FVS 72
__global__ __launch_bounds__(256) void flash_attn(
    const unsigned* __restrict__ qkv_t, const float* __restrict__ uvec,
    const float* __restrict__ BDs, unsigned* __restrict__ ctx_t)
{
    extern __shared__ unsigned sm[];
    unsigned* Qs = sm;                       // [128][FQS]
    unsigned* Ks = Qs + 128 * FQS;           // [2][64][FKS]
    unsigned* Vs = Ks + 2 * 64 * FKS;        // [2][64][FVS]
    unsigned sK = (unsigned)__cvta_generic_to_shared(Ks);
    unsigned sV = (unsigned)__cvta_generic_to_shared(Vs);

    int tid = threadIdx.x, lane = tid & 31, warp = tid >> 5;
    int qid = lane >> 2, qt = lane & 3;
    int bh = blockIdx.y, b = bh >> 4, h = bh & 15;
    int i0 = blockIdx.x * 128;
    int r0 = warp * 16;                       // warp's 16 rows of the i-tile

    // Q tile (u-add fused), 128x64
    #pragma unroll
    for (int i = 0; i < 8; i++) {
        int id = tid + i * 256; int r = id >> 4, c4 = (id & 15) * 4;
        uint4 q = *(const uint4*)(qkv_t + ((size_t)(MEMLEN + i0 + r) * BATCH + b) * QKV3 + h * 64 + c4);
        float4 uv = *(const float4*)(uvec + h * 64 + c4);
        uint4 t = { f2tf(__uint_as_float(q.x) + uv.x), f2tf(__uint_as_float(q.y) + uv.y),
                    f2tf(__uint_as_float(q.z) + uv.z), f2tf(__uint_as_float(q.w) + uv.w) };
        *(uint4*)&Qs[r * FQS + c4] = t;
    }

    int njt = i0 / 64 + 10;
    if (njt > KLEN / 64) njt = KLEN / 64;

    // stage K (permuted) + V (identity) for tile jt into buffer bf
    auto stage = [&](int jt, int bf) {
        int j0 = jt * 64;
        #pragma unroll
        for (int i = 0; i < 4; i++) {
            int id = tid + i * 256; int r = id >> 4, c4 = (id & 15) * 4;
            int w8 = r & 7;
            int keyp = j0 + (r & ~7) + (w8 >> 1) + (w8 & 1) * 4;   // kappa perm
            CPA(sK + ((bf * 64 + r) * FKS + c4) * 4,
                qkv_t + ((size_t)keyp * BATCH + b) * QKV3 + DMODEL + h * 64 + c4);
            CPA(sV + ((bf * 64 + r) * FVS + c4) * 4,
                qkv_t + ((size_t)(j0 + r) * BATCH + b) * QKV3 + 2 * DMODEL + h * 64 + c4);
        }
    };

    stage(0, 0); CPC();

    float m0 = -1e30f, m1 = -1e30f, l0 = 0.0f, l1 = 0.0f;
    float o[8][4];
    #pragma unroll
    for (int nt = 0; nt < 8; nt++)
        #pragma unroll
        for (int t = 0; t < 4; t++) o[nt][t] = 0.0f;

    const float* bdp = BDs + ((size_t)bh * QLEN + i0) * KLEN;
    int irow0 = i0 + r0 + qid, irow1 = irow0 + 8;

    for (int jt = 0; jt < njt; jt++) {
        int buf = jt & 1;
        int j0 = jt * 64;
        if (jt + 1 < njt) stage(jt + 1, buf ^ 1);
        CPC();
        CPW(1);
        __syncthreads();
        const unsigned* Kb = Ks + buf * 64 * FKS;
        const unsigned* Vb = Vs + buf * 64 * FVS;

        // S = Q K^T  (warp rows r0..r0+15, all 64 keys)
        float s[8][4];
        #pragma unroll
        for (int nt = 0; nt < 8; nt++)
            #pragma unroll
            for (int t = 0; t < 4; t++) s[nt][t] = 0.0f;
        #pragma unroll
        for (int kk = 0; kk < 8; kk++) {
            int abase = (r0 + qid) * FQS + kk * 8 + qt;
            unsigned a0 = Qs[abase],     a1 = Qs[abase + 8 * FQS];
            unsigned a2 = Qs[abase + 4], a3 = Qs[abase + 8 * FQS + 4];
            #pragma unroll
            for (int nt = 0; nt < 8; nt++) {
                int bbase = (nt * 8 + qid) * FKS + kk * 8 + qt;
                mma8(s[nt], a0, a1, a2, a3, Kb[bbase], Kb[bbase + 4]);
            }
        }

        // scores: scale + BD + mask; warp-local online softmax
        int msk = (j0 + 63 > i0 + MEMLEN);
        float mx0 = -1e30f, mx1 = -1e30f;
        #pragma unroll
        for (int nt = 0; nt < 8; nt++) {
            int k0 = j0 + nt * 8 + qt, k1 = k0 + 4;
            float v0 = s[nt][0] * ATT_SCALE + bdp[(size_t)(r0 + qid) * KLEN + k0];
            float v1 = s[nt][1] * ATT_SCALE + bdp[(size_t)(r0 + qid) * KLEN + k1];
            float v2 = s[nt][2] * ATT_SCALE + bdp[(size_t)(r0 + qid + 8) * KLEN + k0];
            float v3 = s[nt][3] * ATT_SCALE + bdp[(size_t)(r0 + qid + 8) * KLEN + k1];
            if (msk) {
                if (k0 > irow0 + MEMLEN) v0 = -1e30f;
                if (k1 > irow0 + MEMLEN) v1 = -1e30f;
                if (k0 > irow1 + MEMLEN) v2 = -1e30f;
                if (k1 > irow1 + MEMLEN) v3 = -1e30f;
            }
            s[nt][0] = v0; s[nt][1] = v1; s[nt][2] = v2; s[nt][3] = v3;
            mx0 = fmaxf(mx0, fmaxf(v0, v1));
            mx1 = fmaxf(mx1, fmaxf(v2, v3));
        }
        mx0 = fmaxf(mx0, __shfl_xor_sync(0xffffffffu, mx0, 1));
        mx0 = fmaxf(mx0, __shfl_xor_sync(0xffffffffu, mx0, 2));
        mx1 = fmaxf(mx1, __shfl_xor_sync(0xffffffffu, mx1, 1));
        mx1 = fmaxf(mx1, __shfl_xor_sync(0xffffffffu, mx1, 2));
        float mn0 = fmaxf(m0, mx0), mn1 = fmaxf(m1, mx1);
        float al0 = __expf(m0 - mn0), al1 = __expf(m1 - mn1);
        m0 = mn0; m1 = mn1;
        #pragma unroll
        for (int nt = 0; nt < 8; nt++) {
            o[nt][0] *= al0; o[nt][1] *= al0;
            o[nt][2] *= al1; o[nt][3] *= al1;
        }
        float rs0 = 0.0f, rs1 = 0.0f;
        #pragma unroll
        for (int nt = 0; nt < 8; nt++) {
            float p0 = __expf(s[nt][0] - mn0);
            float p1 = __expf(s[nt][1] - mn0);
            float p2 = __expf(s[nt][2] - mn1);
            float p3 = __expf(s[nt][3] - mn1);
            rs0 += p0 + p1; rs1 += p2 + p3;
            s[nt][0] = __uint_as_float(f2tf(p0));
            s[nt][1] = __uint_as_float(f2tf(p1));
            s[nt][2] = __uint_as_float(f2tf(p2));
            s[nt][3] = __uint_as_float(f2tf(p3));
        }
        rs0 += __shfl_xor_sync(0xffffffffu, rs0, 1);
        rs0 += __shfl_xor_sync(0xffffffffu, rs0, 2);
        rs1 += __shfl_xor_sync(0xffffffffu, rs1, 1);
        rs1 += __shfl_xor_sync(0xffffffffu, rs1, 2);
        l0 = l0 * al0 + rs0;
        l1 = l1 * al1 + rs1;

        // O += P @ V (A-fragment = S fragment thanks to kappa perm)
        #pragma unroll
        for (int kc = 0; kc < 8; kc++) {
            unsigned a0 = __float_as_uint(s[kc][0]);
            unsigned a1 = __float_as_uint(s[kc][2]);
            unsigned a2 = __float_as_uint(s[kc][1]);
            unsigned a3 = __float_as_uint(s[kc][3]);
            #pragma unroll
            for (int nt = 0; nt < 8; nt++) {
                int bbase = (kc * 8 + qt) * FVS + nt * 8 + qid;
                mma8(o[nt], a0, a1, a2, a3, Vb[bbase], Vb[bbase + 4 * FVS]);
            }
        }
        __syncthreads();
    }

    // epilogue
    float inv0 = 1.0f / l0, inv1 = 1.0f / l1;
    int row0 = i0 + r0 + qid;
    #pragma unroll
    for (int nt = 0; nt < 8; nt++) {
        int col = h * 64 + nt * 8 + qt * 2;
        unsigned* p0 = ctx_t + ((size_t)row0 * BATCH + b) * DMODEL + col;
        unsigned* p1 = ctx_t + ((size_t)(row0 + 8) * BATCH + b) * DMODEL + col;
        p0[0] = f2tf(o[nt][0] * inv0); p0[1] = f2tf(o[nt][1] * inv0);
        p1[0] = f2tf(o[nt][2] * inv1); p1[1] = f2tf(o[nt][3] * inv1);
    }
}

// ---------------- layernorm: out = LN(a + b) * g + beta (+ optional tf32 copy) ----------------
__global__ __launch_bounds__(256) void ln_kernel(
    const float* __restrict__ a, const float* __restrict__ bres,
    const float* __restrict__ g, const float* __restrict__ beta,
    float* __restrict__ out, unsigned* __restrict__ out_t)
{
    int row = blockIdx.x;
    int tid = threadIdx.x;
    const float* ap = a    + (size_t)row * DMODEL;
    const float* bp = bres + (size_t)row * DMODEL;
    float x[4];
    float sum = 0.0f;
    #pragma unroll
    for (int t = 0; t < 4; t++) {
        int c = tid + t * 256;
        x[t] = ap[c] + bp[c];
        sum += x[t];
    }
    __shared__ float red[256];
    red[tid] = sum; __syncthreads();
    for (int o = 128; o > 0; o >>= 1) {
        if (tid < o) red[tid] += red[tid + o];
        __syncthreads();
    }
    float mean = red[0] * (1.0f / DMODEL); __syncthreads();
    float vs = 0.0f;
    #pragma unroll
    for (int t = 0; t < 4; t++) { float d = x[t] - mean; vs += d * d; }
    red[tid] = vs; __syncthreads();
    for (int o = 128; o > 0; o >>= 1) {
        if (tid < o) red[tid] += red[tid + o];
        __syncthreads();
    }
    float inv = rsqrtf(red[0] * (1.0f / DMODEL) + LNEPS);
    #pragma unroll
    for (int t = 0; t < 4; t++) {
        int c = tid + t * 256;
        float v = (x[t] - mean) * inv * g[c] + beta[c];
        out[(size_t)row * DMODEL + c] = v;
        if (out_t) out_t[(size_t)row * DMODEL + c] = f2tf(v);
    }
}

// ---------------- launch ----------------
extern "C" void kernel_launch(void* const* d_in, const int* in_sizes, int n_in,
                              void* d_out, int out_size)
{
    const float* inputs = (const float*)d_in[0];
    const float* r      = (const float*)d_in[1];
    const float* u      = (const float*)d_in[2];
    const float* v      = (const float*)d_in[3];
    const float* mem    = (const float*)d_in[4];
    const float* W_qkv  = (const float*)d_in[6];
    const float* W_r    = (const float*)d_in[7];
    const float* W_o    = (const float*)d_in[8];
    const float* ln1_g  = (const float*)d_in[9];
    const float* ln1_b  = (const float*)d_in[10];
    const float* ln2_g  = (const float*)d_in[11];
    const float* ln2_b  = (const float*)d_in[12];
    const float* W1     = (const float*)d_in[13];
    const float* b1     = (const float*)d_in[14];
    const float* W2     = (const float*)d_in[15];
    const float* b2     = (const float*)d_in[16];
    float* out = (float*)d_out;

    unsigned *cat_t, *qkv_t, *rp_t, *ctx_t, *x_t, *h_t;
    unsigned *wqkv_t, *wr_t, *wo_t, *w1_t, *w2_t, *r_t;
    float *BDs, *y, *x, *y2;
    cudaGetSymbolAddress((void**)&cat_t,  g_cat_t);
    cudaGetSymbolAddress((void**)&qkv_t,  g_qkv_t);
    cudaGetSymbolAddress((void**)&rp_t,   g_rp_t);
    cudaGetSymbolAddress((void**)&BDs,    g_BD);
    cudaGetSymbolAddress((void**)&ctx_t,  g_ctx_t);
    cudaGetSymbolAddress((void**)&y,      g_y);
    cudaGetSymbolAddress((void**)&x,      g_x);
    cudaGetSymbolAddress((void**)&x_t,    g_x_t);
    cudaGetSymbolAddress((void**)&h_t,    g_h_t);
    cudaGetSymbolAddress((void**)&y2,     g_y2);
    cudaGetSymbolAddress((void**)&wqkv_t, g_wqkv_t);
    cudaGetSymbolAddress((void**)&wr_t,   g_wr_t);
    cudaGetSymbolAddress((void**)&wo_t,   g_wo_t);
    cudaGetSymbolAddress((void**)&w1_t,   g_w1_t);
    cudaGetSymbolAddress((void**)&w2_t,   g_w2_t);
    cudaGetSymbolAddress((void**)&r_t,    g_r_t);

    const int gemm_smem  = (2 * 128 * GAS + 2 * 32 * GBS) * 4;
    const int bd_smem    = (2 * 128 * BDS) * 4;
    const int flash_smem = (128 * FQS + 2 * 64 * FKS + 2 * 64 * FVS) * 4;
    cudaFuncSetAttribute(gemm_tf32,  cudaFuncAttributeMaxDynamicSharedMemorySize, gemm_smem);
    cudaFuncSetAttribute(bd_tf32,    cudaFuncAttributeMaxDynamicSharedMemorySize, bd_smem);
    cudaFuncSetAttribute(flash_attn, cudaFuncAttributeMaxDynamicSharedMemorySize, flash_smem);

    // 0. round weights + r to tf32 bit patterns
    round_kernel<<<1024, 256>>>(W_qkv, wqkv_t, (size_t)DMODEL * QKV3 / 4);
    round_kernel<<<512,  256>>>(W_r,   wr_t,   (size_t)DMODEL * DMODEL / 4);
    round_kernel<<<512,  256>>>(W_o,   wo_t,   (size_t)DMODEL * DMODEL / 4);
    round_kernel<<<1024, 256>>>(W1,    w1_t,   (size_t)DMODEL * MLPD / 4);
    round_kernel<<<1024, 256>>>(W2,    w2_t,   (size_t)MLPD * DMODEL / 4);
    round_kernel<<<512,  256>>>(r,     r_t,    (size_t)KLEN * DMODEL / 4);

    // 1. cat_t = round([mem; inputs])
    concat_tf32<<<2048, 256>>>(mem, inputs, cat_t);

    // 2. qkv_t = cat_t @ W_qkv (tf32 out; Q-third skipped for mem rows)
    gemm_tf32<<<dim3(QKV3 / 128, (KLEN * BATCH) / 128), 256, gemm_smem>>>(
        cat_t, wqkv_t, nullptr, qkv_t, nullptr, KLEN * BATCH, QKV3, DMODEL, 0, 1);

    // 3. rp_t = r @ W_r (tf32 out)
    gemm_tf32<<<dim3(DMODEL / 128, KLEN / 128), 256, gemm_smem>>>(
        r_t, wr_t, nullptr, rp_t, nullptr, KLEN, DMODEL, DMODEL, 0, 0);

    // 4. BDs (pre-shifted, pre-scaled; v-add fused)
    bd_tf32<<<dim3(KLEN / 128, QLEN / 128, BATCH * NH), 256, bd_smem>>>(qkv_t, rp_t, v, BDs);

    // 5. fused flash attention -> ctx_t (u-add fused)
    flash_attn<<<dim3(QLEN / 128, BATCH * NH), 256, flash_smem>>>(qkv_t, u, BDs, ctx_t);

    // 6. y = ctx_t @ W_o (fp32 out)
    gemm_tf32<<<dim3(DMODEL / 128, (QLEN * BATCH) / 128), 256, gemm_smem>>>(
        ctx_t, wo_t, y, nullptr, nullptr, QLEN * BATCH, DMODEL, DMODEL, 0, 0);

    // 7. x = LN1(inputs + y)  (+ tf32 copy)
    ln_kernel<<<QLEN * BATCH, 256>>>(inputs, y, ln1_g, ln1_b, x, x_t);

    // 8. h_t = relu(x_t @ W1 + b1) (tf32 out)
    gemm_tf32<<<dim3(MLPD / 128, (QLEN * BATCH) / 128), 256, gemm_smem>>>(
        x_t, w1_t, nullptr, h_t, b1, QLEN * BATCH, MLPD, DMODEL, 1, 0);

    // 9. y2 = h_t @ W2 + b2 (fp32 out)
    gemm_tf32<<<dim3(DMODEL / 128, (QLEN * BATCH) / 128), 256, gemm_smem>>>(
        h_t, w2_t, y2, nullptr, b2, QLEN * BATCH, DMODEL, MLPD, 0, 0);

    // 10. out = LN2(x + y2)
    ln_kernel<<<QLEN * BATCH, 256>>>(x, y2, ln2_g, ln2_b, out, nullptr);
}